// round 1
// baseline (speedup 1.0000x reference)
#include <cuda_runtime.h>
#include <cstddef>

#define NPTS 65536
#define BB 4
#define CC 512
#define C3 1536
#define KK 256
#define HH 8
#define DH 64
#define NCH 256   // NPTS/KK

// ---------------- scratch (static device globals; no allocation) ----------------
__device__ float g_qkv[(size_t)NPTS * C3];     // gathered qkv, serialized order
__device__ float g_att[(size_t)NPTS * CC];     // attention output (non-cls rows)
__device__ float g_clsqkv[BB * C3];            // cls token qkv
__device__ float g_clspart[NCH * CC];          // per-chunk cls attention row

// ---------------- GEMM: 128x128 tile, BK=8, 8x8 per thread ----------------
template<bool GATHER, bool SCATTER>
__global__ __launch_bounds__(256)
void sgemm_kernel(const float* __restrict__ A, const float* __restrict__ B,
                  const float* __restrict__ bias, float* __restrict__ C,
                  const int* __restrict__ order, int N, int K)
{
    __shared__ __align__(16) float As[8][128];
    __shared__ __align__(16) float Bs[8][128];
    const int tid = threadIdx.x;
    const int m0 = blockIdx.y * 128;
    const int n0 = blockIdx.x * 128;

    const int arow = tid >> 1;
    const int acol = (tid & 1) << 2;
    int grow = m0 + arow;
    if (GATHER) grow = order[grow];
    const float* Ap = A + (size_t)grow * K + acol;

    const int brow = tid >> 5;
    const int bcol = (tid & 31) << 2;
    const float* Bp = B + (size_t)brow * N + n0 + bcol;

    const int tx = tid & 15;
    const int ty = tid >> 4;

    float acc[8][8] = {};

    for (int k0 = 0; k0 < K; k0 += 8) {
        float4 av = *(const float4*)(Ap + k0);
        float4 bv = *(const float4*)(Bp + (size_t)k0 * N);
        __syncthreads();
        As[acol + 0][arow] = av.x;
        As[acol + 1][arow] = av.y;
        As[acol + 2][arow] = av.z;
        As[acol + 3][arow] = av.w;
        *(float4*)&Bs[brow][bcol] = bv;
        __syncthreads();
        #pragma unroll
        for (int k = 0; k < 8; k++) {
            float a[8], bb[8];
            *(float4*)&a[0]  = *(const float4*)&As[k][ty * 8];
            *(float4*)&a[4]  = *(const float4*)&As[k][ty * 8 + 4];
            *(float4*)&bb[0] = *(const float4*)&Bs[k][tx * 8];
            *(float4*)&bb[4] = *(const float4*)&Bs[k][tx * 8 + 4];
            #pragma unroll
            for (int i = 0; i < 8; i++)
                #pragma unroll
                for (int j = 0; j < 8; j++)
                    acc[i][j] += a[i] * bb[j];
        }
    }

    float bj[8];
    #pragma unroll
    for (int j = 0; j < 8; j++) bj[j] = bias[n0 + tx * 8 + j];

    #pragma unroll
    for (int i = 0; i < 8; i++) {
        int row = m0 + ty * 8 + i;
        int orow = SCATTER ? order[row] : row;
        float* cp = C + (size_t)orow * N + n0 + tx * 8;
        float4 v0, v1;
        v0.x = acc[i][0] + bj[0]; v0.y = acc[i][1] + bj[1];
        v0.z = acc[i][2] + bj[2]; v0.w = acc[i][3] + bj[3];
        v1.x = acc[i][4] + bj[4]; v1.y = acc[i][5] + bj[5];
        v1.z = acc[i][6] + bj[6]; v1.w = acc[i][7] + bj[7];
        *(float4*)cp       = v0;
        *(float4*)(cp + 4) = v1;
    }
}

// ---------------- cls qkv: [B,3C] = cls_tokens @ Wqkv + bqkv ----------------
__global__ __launch_bounds__(128)
void cls_qkv_kernel(const float* __restrict__ cls_tokens,
                    const float* __restrict__ Wqkv,
                    const float* __restrict__ bqkv)
{
    __shared__ float ct[BB * CC];
    for (int i = threadIdx.x; i < BB * CC; i += 128) ct[i] = cls_tokens[i];
    __syncthreads();
    int n = blockIdx.x * 128 + threadIdx.x;   // 12 blocks
    float acc[BB];
    #pragma unroll
    for (int b = 0; b < BB; b++) acc[b] = bqkv[n];
    for (int k = 0; k < CC; k++) {
        float w = Wqkv[(size_t)k * C3 + n];
        #pragma unroll
        for (int b = 0; b < BB; b++) acc[b] += ct[b * CC + k] * w;
    }
    #pragma unroll
    for (int b = 0; b < BB; b++) g_clsqkv[b * C3 + n] = acc[b];
}

// ---------------- attention: one block per (chunk, head), seq = 257 ----------------
#define SK  65     // K/V smem row stride
#define SQ  68     // Q smem row stride (float4-aligned)
#define SSS 292    // score row stride (float4-aligned)
#define KS_F (288 * SK)        // 18720 (rows 257..287 zero-padded)
#define VS_F 16708             // 257*65 = 16705, padded to mult of 4
#define QS_F (32 * SQ)         // 2176
#define SS_F (32 * SSS)        // 9344
#define ATTN_SMEM_BYTES ((KS_F + VS_F + QS_F + SS_F) * 4)

__global__ __launch_bounds__(256)
void attn_kernel(const int* __restrict__ offset)
{
    extern __shared__ float sm[];
    float* Ks = sm;
    float* Vs = Ks + KS_F;
    float* Qs = Vs + VS_F;
    float* Ss = Qs + QS_F;

    const int ci  = blockIdx.x;
    const int h   = blockIdx.y;
    const int tid = threadIdx.x;
    const int cs  = ci * KK;

    int b = 0;
    #pragma unroll
    for (int j = 0; j < BB; j++) b += (offset[j] <= cs) ? 1 : 0;

    const float* qkvbase = g_qkv + (size_t)cs * C3;
    const float* clsrow  = g_clsqkv + b * C3;
    const int koff = CC + h * DH;
    const int voff = 2 * CC + h * DH;

    // load K rows 0..287 (>=257 zero) and V rows 0..256
    for (int idx = tid; idx < 288 * DH; idx += 256) {
        int t = idx >> 6, d = idx & 63;
        float val = 0.f;
        if (t == 0)        val = clsrow[koff + d];
        else if (t <= KK)  val = qkvbase[(size_t)(t - 1) * C3 + koff + d];
        Ks[t * SK + d] = val;
    }
    for (int idx = tid; idx < 257 * DH; idx += 256) {
        int t = idx >> 6, d = idx & 63;
        float val = (t == 0) ? clsrow[voff + d]
                             : qkvbase[(size_t)(t - 1) * C3 + voff + d];
        Vs[t * SK + d] = val;
    }

    const int rg = tid >> 5;   // warp id -> rows rg*4..rg*4+3
    const int cg = tid & 31;   // lane

    for (int qt = 0; qt < 9; qt++) {
        __syncthreads();
        // load Q tile (scaled)
        for (int idx = tid; idx < 32 * DH; idx += 256) {
            int r = idx >> 6, d = idx & 63;
            int tau = qt * 32 + r;
            float val = 0.f;
            if (tau == 0)       val = clsrow[h * DH + d];
            else if (tau <= KK) val = qkvbase[(size_t)(tau - 1) * C3 + h * DH + d];
            Qs[r * SQ + d] = val * 0.125f;   // dh^-0.5
        }
        __syncthreads();

        // S = Q @ K^T  (3 passes of 96 cols, micro 4r x 3c)
        const float* qrow0 = Qs + (rg * 4) * SQ;
        for (int p = 0; p < 3; p++) {
            float acc[4][3] = {};
            const int j0 = p * 96 + cg;
            const float* kp0 = Ks + (size_t)j0 * SK;
            const float* kp1 = kp0 + 32 * SK;
            const float* kp2 = kp0 + 64 * SK;
            #pragma unroll
            for (int d4 = 0; d4 < DH; d4 += 4) {
                float qv[4][4];
                *(float4*)qv[0] = *(const float4*)(qrow0 + 0 * SQ + d4);
                *(float4*)qv[1] = *(const float4*)(qrow0 + 1 * SQ + d4);
                *(float4*)qv[2] = *(const float4*)(qrow0 + 2 * SQ + d4);
                *(float4*)qv[3] = *(const float4*)(qrow0 + 3 * SQ + d4);
                #pragma unroll
                for (int dd = 0; dd < 4; dd++) {
                    float k0v = kp0[d4 + dd];
                    float k1v = kp1[d4 + dd];
                    float k2v = kp2[d4 + dd];
                    #pragma unroll
                    for (int rr = 0; rr < 4; rr++) {
                        acc[rr][0] += qv[rr][dd] * k0v;
                        acc[rr][1] += qv[rr][dd] * k1v;
                        acc[rr][2] += qv[rr][dd] * k2v;
                    }
                }
            }
            #pragma unroll
            for (int rr = 0; rr < 4; rr++)
                #pragma unroll
                for (int cc = 0; cc < 3; cc++)
                    Ss[(rg * 4 + rr) * SSS + j0 + 32 * cc] = acc[rr][cc];
        }
        __syncthreads();

        // softmax (warp rg handles its 4 rows; cols 0..256)
        #pragma unroll
        for (int rr = 0; rr < 4; rr++) {
            int r = rg * 4 + rr;
            int tau = qt * 32 + r;
            if (tau > KK) break;
            float* srow = Ss + r * SSS;
            float m = -1e30f;
            for (int j = cg; j < 257; j += 32) m = fmaxf(m, srow[j]);
            #pragma unroll
            for (int o = 16; o; o >>= 1) m = fmaxf(m, __shfl_xor_sync(0xffffffffu, m, o));
            float sum = 0.f;
            for (int j = cg; j < 257; j += 32) {
                float e = __expf(srow[j] - m);
                srow[j] = e;
                sum += e;
            }
            #pragma unroll
            for (int o = 16; o; o >>= 1) sum += __shfl_xor_sync(0xffffffffu, sum, o);
            float inv = 1.f / sum;
            for (int j = cg; j < 257; j += 32) srow[j] *= inv;
        }
        __syncthreads();

        // O = P @ V  (cols cg, cg+32; kk unrolled x4 with float4 P loads)
        float o0[4] = {}, o1[4] = {};
        const float* prow0 = Ss + (rg * 4) * SSS;
        for (int kk = 0; kk < 256; kk += 4) {
            float pv[4][4];
            *(float4*)pv[0] = *(const float4*)(prow0 + 0 * SSS + kk);
            *(float4*)pv[1] = *(const float4*)(prow0 + 1 * SSS + kk);
            *(float4*)pv[2] = *(const float4*)(prow0 + 2 * SSS + kk);
            *(float4*)pv[3] = *(const float4*)(prow0 + 3 * SSS + kk);
            #pragma unroll
            for (int dd = 0; dd < 4; dd++) {
                float v0 = Vs[(kk + dd) * SK + cg];
                float v1 = Vs[(kk + dd) * SK + cg + 32];
                #pragma unroll
                for (int rr = 0; rr < 4; rr++) {
                    o0[rr] += pv[rr][dd] * v0;
                    o1[rr] += pv[rr][dd] * v1;
                }
            }
        }
        {   // tail kk = 256
            float v0 = Vs[256 * SK + cg];
            float v1 = Vs[256 * SK + cg + 32];
            #pragma unroll
            for (int rr = 0; rr < 4; rr++) {
                float pv = prow0[rr * SSS + 256];
                o0[rr] += pv * v0;
                o1[rr] += pv * v1;
            }
        }

        #pragma unroll
        for (int rr = 0; rr < 4; rr++) {
            int tau = qt * 32 + rg * 4 + rr;
            if (tau == 0) {
                g_clspart[ci * CC + h * DH + cg]      = o0[rr];
                g_clspart[ci * CC + h * DH + cg + 32] = o1[rr];
            } else if (tau <= KK) {
                float* dst = g_att + ((size_t)(cs + tau - 1)) * CC + h * DH;
                dst[cg]      = o0[rr];
                dst[cg + 32] = o1[rr];
            }
        }
    }
}

// ---------------- cls reduce: cls_feat[b,c] = mean over chunks of batch b ----------------
__global__ __launch_bounds__(256)
void cls_reduce_kernel(const int* __restrict__ offset, float* __restrict__ out_cls)
{
    int gid = blockIdx.x * 256 + threadIdx.x;   // 8 blocks -> B*C = 2048
    int b = gid >> 9;       // / CC
    int c = gid & (CC - 1);
    int start = (b == 0) ? 0 : offset[b - 1];
    int end = offset[b];
    int ch0 = start / KK, ch1 = end / KK;
    float s = 0.f;
    for (int ch = ch0; ch < ch1; ch++) s += g_clspart[ch * CC + c];
    out_cls[gid] = s / (float)(ch1 - ch0);
}

// ---------------- launch ----------------
extern "C" void kernel_launch(void* const* d_in, const int* in_sizes, int n_in,
                              void* d_out, int out_size)
{
    const float* feat       = (const float*)d_in[0];
    const float* cls_tokens = (const float*)d_in[1];
    const float* Wqkv       = (const float*)d_in[2];
    const float* bqkv       = (const float*)d_in[3];
    const float* Wproj      = (const float*)d_in[4];
    const float* bproj      = (const float*)d_in[5];
    const int*   order      = (const int*)d_in[6];
    // d_in[7] = inverse (unused: scatter via order), d_in[8] = offset
    const int*   offset     = (const int*)d_in[8];

    float* out_feat = (float*)d_out;
    float* out_cls  = out_feat + (size_t)NPTS * CC;

    void* qkvp = nullptr;
    void* attp = nullptr;
    cudaGetSymbolAddress(&qkvp, g_qkv);
    cudaGetSymbolAddress(&attp, g_att);

    cudaFuncSetAttribute(attn_kernel, cudaFuncAttributeMaxDynamicSharedMemorySize,
                         ATTN_SMEM_BYTES);

    // 1. cls token qkv
    cls_qkv_kernel<<<C3 / 128, 128>>>(cls_tokens, Wqkv, bqkv);
    // 2. gathered qkv GEMM: [N,3C] = feat[order] @ Wqkv + bqkv
    sgemm_kernel<true, false><<<dim3(C3 / 128, NPTS / 128), 256>>>(
        feat, Wqkv, bqkv, (float*)qkvp, order, C3, CC);
    // 3. per-chunk attention
    attn_kernel<<<dim3(NCH, HH), 256, ATTN_SMEM_BYTES>>>(offset);
    // 4. proj GEMM with scatter: feat_out[order[j]] = g_att[j] @ Wproj + bproj
    sgemm_kernel<false, true><<<dim3(CC / 128, NPTS / 128), 256>>>(
        (const float*)attp, Wproj, bproj, out_feat, order, CC, CC);
    // 5. cls reduction
    cls_reduce_kernel<<<(BB * CC) / 256, 256>>>(offset, out_cls);
}

// round 3
// speedup vs baseline: 1.3579x; 1.3579x over previous
#include <cuda_runtime.h>
#include <cuda_bf16.h>
#include <cstdint>
#include <cstddef>

#define NPTS 65536
#define BB 4
#define CC 512
#define C3 1536
#define KK 256
#define HH 8
#define DH 64
#define NCH 256   // NPTS/KK

// ---------------- scratch (static device globals; no allocation) ----------------
__device__ float g_qkv[(size_t)NPTS * C3];     // gathered qkv, serialized order
__device__ float g_att[(size_t)NPTS * CC];     // attention output (non-cls rows)
__device__ float g_clsqkv[BB * C3];            // cls token qkv
__device__ float g_clspart[NCH * CC];          // per-chunk cls attention row
__device__ __nv_bfloat16 g_WqkvT_h[(size_t)C3 * CC];
__device__ __nv_bfloat16 g_WqkvT_l[(size_t)C3 * CC];
__device__ __nv_bfloat16 g_WprojT_h[(size_t)CC * CC];
__device__ __nv_bfloat16 g_WprojT_l[(size_t)CC * CC];

// =============== helpers ===============
__device__ __forceinline__ uint32_t smem_u32(const void* p) {
    uint32_t a;
    asm("{ .reg .u64 t; cvta.to.shared.u64 t, %1; cvt.u32.u64 %0, t; }" : "=r"(a) : "l"(p));
    return a;
}
__device__ __forceinline__ void ldsm_x4(uint32_t* r, uint32_t addr) {
    asm volatile("ldmatrix.sync.aligned.m8n8.x4.shared.b16 {%0,%1,%2,%3}, [%4];"
                 : "=r"(r[0]), "=r"(r[1]), "=r"(r[2]), "=r"(r[3]) : "r"(addr));
}
__device__ __forceinline__ void ldsm_x2(uint32_t* r, uint32_t addr) {
    asm volatile("ldmatrix.sync.aligned.m8n8.x2.shared.b16 {%0,%1}, [%2];"
                 : "=r"(r[0]), "=r"(r[1]) : "r"(addr));
}
__device__ __forceinline__ void mma_bf16(float* c, const uint32_t* a, const uint32_t* b) {
    asm volatile(
        "mma.sync.aligned.m16n8k16.row.col.f32.bf16.bf16.f32 "
        "{%0,%1,%2,%3}, {%4,%5,%6,%7}, {%8,%9}, {%0,%1,%2,%3};"
        : "+f"(c[0]), "+f"(c[1]), "+f"(c[2]), "+f"(c[3])
        : "r"(a[0]), "r"(a[1]), "r"(a[2]), "r"(a[3]), "r"(b[0]), "r"(b[1]));
}

// ---------------- W transpose + bf16 split: W[K,N] fp32 -> T[N,K] hi/lo ----------------
__global__ __launch_bounds__(256)
void conv_wt_kernel(const float* __restrict__ W, __nv_bfloat16* __restrict__ Th,
                    __nv_bfloat16* __restrict__ Tl, int K, int N)
{
    __shared__ float t[32][33];
    int n0 = blockIdx.x * 32, k0 = blockIdx.y * 32;
    int tx = threadIdx.x & 31, ty = threadIdx.x >> 5;
    #pragma unroll
    for (int j = 0; j < 32; j += 8)
        t[ty + j][tx] = W[(size_t)(k0 + ty + j) * N + n0 + tx];
    __syncthreads();
    #pragma unroll
    for (int j = 0; j < 32; j += 8) {
        int n = n0 + ty + j, k = k0 + tx;
        float v = t[tx][ty + j];
        __nv_bfloat16 h = __float2bfloat16(v);
        __nv_bfloat16 l = __float2bfloat16(v - __bfloat162float(h));
        Th[(size_t)n * K + k] = h;
        Tl[(size_t)n * K + k] = l;
    }
}

// ---------------- mma.sync GEMM: 128x128 tile, Kchunk=32, split-bf16 x3 ----------------
// smem: [0,512) bias f32[128] | [512,1024) rowidx i32[128] | [1024,..) 2 stages
// stage: Ah[128][40]bf16 | Al | Bh[128][40] | Bl   (stride 80B, 10240B per tile)
#define ASTRIDE 80
#define TILEB   (128 * ASTRIDE)      // 10240
#define STAGEB  (4 * TILEB)          // 40960
#define SM_TILES 1024
#define GSMEM   (SM_TILES + 2 * STAGEB)   // 82944

template<bool GATHER, bool SCATTER>
__global__ __launch_bounds__(256)
void mma_gemm_kernel(const float* __restrict__ A, const __nv_bfloat16* __restrict__ Bh,
                     const __nv_bfloat16* __restrict__ Bl, const float* __restrict__ bias,
                     float* __restrict__ C, const int* __restrict__ order, int Ntot)
{
    extern __shared__ char sm[];
    const uint32_t sb = smem_u32(sm);
    const int tid = threadIdx.x, wid = tid >> 5, lane = tid & 31;
    const int n0 = blockIdx.x * 128, m0 = blockIdx.y * 128;
    float* bias_s = (float*)sm;
    int*   rowidx = (int*)(sm + 512);

    if (tid < 128) {
        rowidx[tid] = (GATHER || SCATTER) ? order[m0 + tid] : (m0 + tid);
        bias_s[tid] = bias[n0 + tid];
    }
    __syncthreads();

    // per-thread load coordinates
    int aR[4], aU[4], bW[4], bR[4], bU[4];
    #pragma unroll
    for (int i = 0; i < 4; i++) {
        int idx = tid + i * 256;
        aR[i] = idx >> 3;  aU[i] = idx & 7;             // A: 1024 float4 units
        bW[i] = idx >> 9;  bR[i] = (idx >> 2) & 127;    // B: 1024 uint4 units
        bU[i] = idx & 3;
    }

    const int wm = (wid & 1) * 64;
    const int wn = (wid >> 1) * 32;

    float acc[4][4][4];
    #pragma unroll
    for (int nt = 0; nt < 4; nt++) {
        float b0 = bias_s[wn + nt * 8 + 2 * (lane & 3)];
        float b1 = bias_s[wn + nt * 8 + 2 * (lane & 3) + 1];
        #pragma unroll
        for (int mt = 0; mt < 4; mt++) {
            acc[mt][nt][0] = b0; acc[mt][nt][1] = b1;
            acc[mt][nt][2] = b0; acc[mt][nt][3] = b1;
        }
    }

    float4 areg[4];
    uint4  breg[4];

    auto load_regs = [&](int k0) {
        #pragma unroll
        for (int i = 0; i < 4; i++) {
            int grow = GATHER ? rowidx[aR[i]] : (m0 + aR[i]);
            areg[i] = *(const float4*)(A + (size_t)grow * CC + k0 + aU[i] * 4);
        }
        #pragma unroll
        for (int i = 0; i < 4; i++) {
            const __nv_bfloat16* src =
                (bW[i] ? Bl : Bh) + (size_t)(n0 + bR[i]) * CC + k0 + bU[i] * 8;
            breg[i] = *(const uint4*)src;
        }
    };
    auto store_smem = [&](int stage) {
        char* base = sm + SM_TILES + stage * STAGEB;
        #pragma unroll
        for (int i = 0; i < 4; i++) {
            float4 v = areg[i];
            __nv_bfloat162 h01 = __floats2bfloat162_rn(v.x, v.y);
            __nv_bfloat162 h23 = __floats2bfloat162_rn(v.z, v.w);
            __nv_bfloat162 l01 = __floats2bfloat162_rn(v.x - __low2float(h01),
                                                       v.y - __high2float(h01));
            __nv_bfloat162 l23 = __floats2bfloat162_rn(v.z - __low2float(h23),
                                                       v.w - __high2float(h23));
            int off = aR[i] * ASTRIDE + aU[i] * 8;
            *(uint2*)(base + off) =
                make_uint2(*(uint32_t*)&h01, *(uint32_t*)&h23);
            *(uint2*)(base + TILEB + off) =
                make_uint2(*(uint32_t*)&l01, *(uint32_t*)&l23);
        }
        #pragma unroll
        for (int i = 0; i < 4; i++) {
            int off = 2 * TILEB + bW[i] * TILEB + bR[i] * ASTRIDE + bU[i] * 16;
            *(uint4*)(base + off) = breg[i];
        }
    };

    load_regs(0);
    store_smem(0);
    __syncthreads();

    const uint32_t a_lm = sb + SM_TILES + (wm + (lane & 15)) * ASTRIDE + ((lane >> 4) & 1) * 16;
    const uint32_t b_lm = sb + SM_TILES + 2 * TILEB + (wn + (lane & 7)) * ASTRIDE
                          + ((lane >> 3) & 1) * 16;

    const int NC = CC / 32;   // 16
    #pragma unroll 1
    for (int c = 0; c < NC; c++) {
        if (c + 1 < NC) load_regs((c + 1) * 32);
        const uint32_t abase = a_lm + (c & 1) * STAGEB;
        const uint32_t bbase = b_lm + (c & 1) * STAGEB;
        #pragma unroll
        for (int ks = 0; ks < 2; ks++) {
            const int ko = ks * 32;   // 16 bf16 = 32 bytes
            uint32_t ah[4][4], al[4][4], bh[4][2], bl[4][2];
            #pragma unroll
            for (int mt = 0; mt < 4; mt++) {
                ldsm_x4(ah[mt], abase + mt * 16 * ASTRIDE + ko);
                ldsm_x4(al[mt], abase + TILEB + mt * 16 * ASTRIDE + ko);
            }
            #pragma unroll
            for (int nt = 0; nt < 4; nt++) {
                ldsm_x2(bh[nt], bbase + nt * 8 * ASTRIDE + ko);
                ldsm_x2(bl[nt], bbase + TILEB + nt * 8 * ASTRIDE + ko);
            }
            #pragma unroll
            for (int mt = 0; mt < 4; mt++)
                #pragma unroll
                for (int nt = 0; nt < 4; nt++) {
                    mma_bf16(acc[mt][nt], ah[mt], bh[nt]);
                    mma_bf16(acc[mt][nt], ah[mt], bl[nt]);
                    mma_bf16(acc[mt][nt], al[mt], bh[nt]);
                }
        }
        __syncthreads();
        if (c + 1 < NC) {
            store_smem((c + 1) & 1);
            __syncthreads();
        }
    }

    // epilogue
    #pragma unroll
    for (int mt = 0; mt < 4; mt++) {
        int lrow = wm + mt * 16 + (lane >> 2);
        int d0 = SCATTER ? rowidx[lrow]     : (m0 + lrow);
        int d1 = SCATTER ? rowidx[lrow + 8] : (m0 + lrow + 8);
        #pragma unroll
        for (int nt = 0; nt < 4; nt++) {
            int col = n0 + wn + nt * 8 + 2 * (lane & 3);
            *(float2*)(C + (size_t)d0 * Ntot + col) =
                make_float2(acc[mt][nt][0], acc[mt][nt][1]);
            *(float2*)(C + (size_t)d1 * Ntot + col) =
                make_float2(acc[mt][nt][2], acc[mt][nt][3]);
        }
    }
}

// ---------------- cls qkv: [B,3C] = cls_tokens @ Wqkv + bqkv ----------------
__global__ __launch_bounds__(128)
void cls_qkv_kernel(const float* __restrict__ cls_tokens,
                    const float* __restrict__ Wqkv,
                    const float* __restrict__ bqkv)
{
    __shared__ float ct[BB * CC];
    for (int i = threadIdx.x; i < BB * CC; i += 128) ct[i] = cls_tokens[i];
    __syncthreads();
    int n = blockIdx.x * 128 + threadIdx.x;
    float acc[BB];
    #pragma unroll
    for (int b = 0; b < BB; b++) acc[b] = bqkv[n];
    for (int k = 0; k < CC; k++) {
        float w = Wqkv[(size_t)k * C3 + n];
        #pragma unroll
        for (int b = 0; b < BB; b++) acc[b] += ct[b * CC + k] * w;
    }
    #pragma unroll
    for (int b = 0; b < BB; b++) g_clsqkv[b * C3 + n] = acc[b];
}

// ---------------- attention: one block per (chunk, head), seq = 257 ----------------
#define SK  65
#define SQ  68
#define SSS 292
#define KS_F (288 * SK)
#define VS_F 16708
#define QS_F (32 * SQ)
#define SS_F (32 * SSS)
#define ATTN_SMEM_BYTES ((KS_F + VS_F + QS_F + SS_F) * 4)

__global__ __launch_bounds__(256)
void attn_kernel(const int* __restrict__ offset)
{
    extern __shared__ float smf[];
    float* Ks = smf;
    float* Vs = Ks + KS_F;
    float* Qs = Vs + VS_F;
    float* Ss = Qs + QS_F;

    const int ci  = blockIdx.x;
    const int h   = blockIdx.y;
    const int tid = threadIdx.x;
    const int cs  = ci * KK;

    int b = 0;
    #pragma unroll
    for (int j = 0; j < BB; j++) b += (offset[j] <= cs) ? 1 : 0;

    const float* qkvbase = g_qkv + (size_t)cs * C3;
    const float* clsrow  = g_clsqkv + b * C3;
    const int koff = CC + h * DH;
    const int voff = 2 * CC + h * DH;

    for (int idx = tid; idx < 288 * DH; idx += 256) {
        int t = idx >> 6, d = idx & 63;
        float val = 0.f;
        if (t == 0)        val = clsrow[koff + d];
        else if (t <= KK)  val = qkvbase[(size_t)(t - 1) * C3 + koff + d];
        Ks[t * SK + d] = val;
    }
    for (int idx = tid; idx < 257 * DH; idx += 256) {
        int t = idx >> 6, d = idx & 63;
        float val = (t == 0) ? clsrow[voff + d]
                             : qkvbase[(size_t)(t - 1) * C3 + voff + d];
        Vs[t * SK + d] = val;
    }

    const int rg = tid >> 5;
    const int cg = tid & 31;

    for (int qt = 0; qt < 9; qt++) {
        __syncthreads();
        for (int idx = tid; idx < 32 * DH; idx += 256) {
            int r = idx >> 6, d = idx & 63;
            int tau = qt * 32 + r;
            float val = 0.f;
            if (tau == 0)       val = clsrow[h * DH + d];
            else if (tau <= KK) val = qkvbase[(size_t)(tau - 1) * C3 + h * DH + d];
            Qs[r * SQ + d] = val * 0.125f;
        }
        __syncthreads();

        const float* qrow0 = Qs + (rg * 4) * SQ;
        for (int p = 0; p < 3; p++) {
            float acc[4][3] = {};
            const int j0 = p * 96 + cg;
            const float* kp0 = Ks + (size_t)j0 * SK;
            const float* kp1 = kp0 + 32 * SK;
            const float* kp2 = kp0 + 64 * SK;
            #pragma unroll
            for (int d4 = 0; d4 < DH; d4 += 4) {
                float qv[4][4];
                *(float4*)qv[0] = *(const float4*)(qrow0 + 0 * SQ + d4);
                *(float4*)qv[1] = *(const float4*)(qrow0 + 1 * SQ + d4);
                *(float4*)qv[2] = *(const float4*)(qrow0 + 2 * SQ + d4);
                *(float4*)qv[3] = *(const float4*)(qrow0 + 3 * SQ + d4);
                #pragma unroll
                for (int dd = 0; dd < 4; dd++) {
                    float k0v = kp0[d4 + dd];
                    float k1v = kp1[d4 + dd];
                    float k2v = kp2[d4 + dd];
                    #pragma unroll
                    for (int rr = 0; rr < 4; rr++) {
                        acc[rr][0] += qv[rr][dd] * k0v;
                        acc[rr][1] += qv[rr][dd] * k1v;
                        acc[rr][2] += qv[rr][dd] * k2v;
                    }
                }
            }
            #pragma unroll
            for (int rr = 0; rr < 4; rr++)
                #pragma unroll
                for (int cc = 0; cc < 3; cc++)
                    Ss[(rg * 4 + rr) * SSS + j0 + 32 * cc] = acc[rr][cc];
        }
        __syncthreads();

        #pragma unroll
        for (int rr = 0; rr < 4; rr++) {
            int r = rg * 4 + rr;
            int tau = qt * 32 + r;
            if (tau > KK) break;
            float* srow = Ss + r * SSS;
            float m = -1e30f;
            for (int j = cg; j < 257; j += 32) m = fmaxf(m, srow[j]);
            #pragma unroll
            for (int o = 16; o; o >>= 1) m = fmaxf(m, __shfl_xor_sync(0xffffffffu, m, o));
            float sum = 0.f;
            for (int j = cg; j < 257; j += 32) {
                float e = __expf(srow[j] - m);
                srow[j] = e;
                sum += e;
            }
            #pragma unroll
            for (int o = 16; o; o >>= 1) sum += __shfl_xor_sync(0xffffffffu, sum, o);
            float inv = 1.f / sum;
            for (int j = cg; j < 257; j += 32) srow[j] *= inv;
        }
        __syncthreads();

        float o0[4] = {}, o1[4] = {};
        const float* prow0 = Ss + (rg * 4) * SSS;
        for (int kk2 = 0; kk2 < 256; kk2 += 4) {
            float pv[4][4];
            *(float4*)pv[0] = *(const float4*)(prow0 + 0 * SSS + kk2);
            *(float4*)pv[1] = *(const float4*)(prow0 + 1 * SSS + kk2);
            *(float4*)pv[2] = *(const float4*)(prow0 + 2 * SSS + kk2);
            *(float4*)pv[3] = *(const float4*)(prow0 + 3 * SSS + kk2);
            #pragma unroll
            for (int dd = 0; dd < 4; dd++) {
                float v0 = Vs[(kk2 + dd) * SK + cg];
                float v1 = Vs[(kk2 + dd) * SK + cg + 32];
                #pragma unroll
                for (int rr = 0; rr < 4; rr++) {
                    o0[rr] += pv[rr][dd] * v0;
                    o1[rr] += pv[rr][dd] * v1;
                }
            }
        }
        {
            float v0 = Vs[256 * SK + cg];
            float v1 = Vs[256 * SK + cg + 32];
            #pragma unroll
            for (int rr = 0; rr < 4; rr++) {
                float pv = prow0[rr * SSS + 256];
                o0[rr] += pv * v0;
                o1[rr] += pv * v1;
            }
        }

        #pragma unroll
        for (int rr = 0; rr < 4; rr++) {
            int tau = qt * 32 + rg * 4 + rr;
            if (tau == 0) {
                g_clspart[ci * CC + h * DH + cg]      = o0[rr];
                g_clspart[ci * CC + h * DH + cg + 32] = o1[rr];
            } else if (tau <= KK) {
                float* dst = g_att + ((size_t)(cs + tau - 1)) * CC + h * DH;
                dst[cg]      = o0[rr];
                dst[cg + 32] = o1[rr];
            }
        }
    }
}

// ---------------- cls reduce ----------------
__global__ __launch_bounds__(256)
void cls_reduce_kernel(const int* __restrict__ offset, float* __restrict__ out_cls)
{
    int gid = blockIdx.x * 256 + threadIdx.x;
    int b = gid >> 9;
    int c = gid & (CC - 1);
    int start = (b == 0) ? 0 : offset[b - 1];
    int end = offset[b];
    int ch0 = start / KK, ch1 = end / KK;
    float s = 0.f;
    for (int ch = ch0; ch < ch1; ch++) s += g_clspart[ch * CC + c];
    out_cls[gid] = s / (float)(ch1 - ch0);
}

// ---------------- launch ----------------
extern "C" void kernel_launch(void* const* d_in, const int* in_sizes, int n_in,
                              void* d_out, int out_size)
{
    const float* feat       = (const float*)d_in[0];
    const float* cls_tokens = (const float*)d_in[1];
    const float* Wqkv       = (const float*)d_in[2];
    const float* bqkv       = (const float*)d_in[3];
    const float* Wproj      = (const float*)d_in[4];
    const float* bproj      = (const float*)d_in[5];
    const int*   order      = (const int*)d_in[6];
    const int*   offset     = (const int*)d_in[8];

    float* out_feat = (float*)d_out;
    float* out_cls  = out_feat + (size_t)NPTS * CC;

    void *qkvp = nullptr, *attp = nullptr;
    void *wqh = nullptr, *wql = nullptr, *wph = nullptr, *wpl = nullptr;
    cudaGetSymbolAddress(&qkvp, g_qkv);
    cudaGetSymbolAddress(&attp, g_att);
    cudaGetSymbolAddress(&wqh, g_WqkvT_h);
    cudaGetSymbolAddress(&wql, g_WqkvT_l);
    cudaGetSymbolAddress(&wph, g_WprojT_h);
    cudaGetSymbolAddress(&wpl, g_WprojT_l);

    cudaFuncSetAttribute(attn_kernel, cudaFuncAttributeMaxDynamicSharedMemorySize,
                         ATTN_SMEM_BYTES);
    cudaFuncSetAttribute(mma_gemm_kernel<true, false>,
                         cudaFuncAttributeMaxDynamicSharedMemorySize, GSMEM);
    cudaFuncSetAttribute(mma_gemm_kernel<false, true>,
                         cudaFuncAttributeMaxDynamicSharedMemorySize, GSMEM);

    // 0. transpose + bf16-split weights
    conv_wt_kernel<<<dim3(C3 / 32, CC / 32), 256>>>(
        Wqkv, (__nv_bfloat16*)wqh, (__nv_bfloat16*)wql, CC, C3);
    conv_wt_kernel<<<dim3(CC / 32, CC / 32), 256>>>(
        Wproj, (__nv_bfloat16*)wph, (__nv_bfloat16*)wpl, CC, CC);
    // 1. cls token qkv
    cls_qkv_kernel<<<C3 / 128, 128>>>(cls_tokens, Wqkv, bqkv);
    // 2. gathered qkv GEMM (mma.sync): g_qkv[m] = feat[order[m]] @ Wqkv + bqkv
    mma_gemm_kernel<true, false><<<dim3(C3 / 128, NPTS / 128), 256, GSMEM>>>(
        feat, (const __nv_bfloat16*)wqh, (const __nv_bfloat16*)wql,
        bqkv, (float*)qkvp, order, C3);
    // 3. per-chunk attention
    attn_kernel<<<dim3(NCH, HH), 256, ATTN_SMEM_BYTES>>>(offset);
    // 4. proj GEMM (mma.sync) with scatter
    mma_gemm_kernel<false, true><<<dim3(CC / 128, NPTS / 128), 256, GSMEM>>>(
        (const float*)attp, (const __nv_bfloat16*)wph, (const __nv_bfloat16*)wpl,
        bproj, out_feat, order, CC);
    // 5. cls reduction
    cls_reduce_kernel<<<(BB * CC) / 256, 256>>>(offset, out_cls);
}

// round 4
// speedup vs baseline: 2.6425x; 1.9460x over previous
#include <cuda_runtime.h>
#include <cuda_bf16.h>
#include <cstdint>
#include <cstddef>

#define NPTS 65536
#define BB 4
#define CC 512
#define C3 1536
#define KK 256
#define HH 8
#define DH 64
#define NCH 256   // NPTS/KK

// ---------------- scratch (static device globals; no allocation) ----------------
__device__ float g_qkv[(size_t)NPTS * C3];     // gathered qkv, serialized order
__device__ float g_att[(size_t)NPTS * CC];     // attention output (non-cls rows)
__device__ float g_clsqkv[BB * C3];            // cls token qkv
__device__ float g_clspart[NCH * CC];          // per-chunk cls attention row
__device__ __nv_bfloat16 g_WqkvT_h[(size_t)C3 * CC];
__device__ __nv_bfloat16 g_WqkvT_l[(size_t)C3 * CC];
__device__ __nv_bfloat16 g_WprojT_h[(size_t)CC * CC];
__device__ __nv_bfloat16 g_WprojT_l[(size_t)CC * CC];

// =============== helpers ===============
__device__ __forceinline__ uint32_t smem_u32(const void* p) {
    uint32_t a;
    asm("{ .reg .u64 t; cvta.to.shared.u64 t, %1; cvt.u32.u64 %0, t; }" : "=r"(a) : "l"(p));
    return a;
}
__device__ __forceinline__ void ldsm_x4(uint32_t* r, uint32_t addr) {
    asm volatile("ldmatrix.sync.aligned.m8n8.x4.shared.b16 {%0,%1,%2,%3}, [%4];"
                 : "=r"(r[0]), "=r"(r[1]), "=r"(r[2]), "=r"(r[3]) : "r"(addr));
}
__device__ __forceinline__ void ldsm_x2(uint32_t* r, uint32_t addr) {
    asm volatile("ldmatrix.sync.aligned.m8n8.x2.shared.b16 {%0,%1}, [%2];"
                 : "=r"(r[0]), "=r"(r[1]) : "r"(addr));
}
__device__ __forceinline__ void ldsm_x2_t(uint32_t* r, uint32_t addr) {
    asm volatile("ldmatrix.sync.aligned.m8n8.x2.trans.shared.b16 {%0,%1}, [%2];"
                 : "=r"(r[0]), "=r"(r[1]) : "r"(addr));
}
__device__ __forceinline__ void mma_bf16(float* c, const uint32_t* a, const uint32_t* b) {
    asm volatile(
        "mma.sync.aligned.m16n8k16.row.col.f32.bf16.bf16.f32 "
        "{%0,%1,%2,%3}, {%4,%5,%6,%7}, {%8,%9}, {%0,%1,%2,%3};"
        : "+f"(c[0]), "+f"(c[1]), "+f"(c[2]), "+f"(c[3])
        : "r"(a[0]), "r"(a[1]), "r"(a[2]), "r"(a[3]), "r"(b[0]), "r"(b[1]));
}
// pack two floats to bf16x2 hi, return hi, write lo residual pair
__device__ __forceinline__ uint32_t split_pack(float x, float y, uint32_t* lo) {
    __nv_bfloat162 hh = __floats2bfloat162_rn(x, y);
    __nv_bfloat162 ll = __floats2bfloat162_rn(x - __low2float(hh), y - __high2float(hh));
    *lo = *reinterpret_cast<uint32_t*>(&ll);
    return *reinterpret_cast<uint32_t*>(&hh);
}

// ---------------- W transpose + bf16 split: W[K,N] fp32 -> T[N,K] hi/lo ----------------
__global__ __launch_bounds__(256)
void conv_wt_kernel(const float* __restrict__ W, __nv_bfloat16* __restrict__ Th,
                    __nv_bfloat16* __restrict__ Tl, int K, int N)
{
    __shared__ float t[32][33];
    int n0 = blockIdx.x * 32, k0 = blockIdx.y * 32;
    int tx = threadIdx.x & 31, ty = threadIdx.x >> 5;
    #pragma unroll
    for (int j = 0; j < 32; j += 8)
        t[ty + j][tx] = W[(size_t)(k0 + ty + j) * N + n0 + tx];
    __syncthreads();
    #pragma unroll
    for (int j = 0; j < 32; j += 8) {
        int n = n0 + ty + j, k = k0 + tx;
        float v = t[tx][ty + j];
        __nv_bfloat16 h = __float2bfloat16(v);
        __nv_bfloat16 l = __float2bfloat16(v - __bfloat162float(h));
        Th[(size_t)n * K + k] = h;
        Tl[(size_t)n * K + k] = l;
    }
}

// ---------------- mma.sync GEMM (unchanged from R3) ----------------
#define ASTRIDE 80
#define TILEB   (128 * ASTRIDE)
#define STAGEB  (4 * TILEB)
#define SM_TILES 1024
#define GSMEM   (SM_TILES + 2 * STAGEB)

template<bool GATHER, bool SCATTER>
__global__ __launch_bounds__(256)
void mma_gemm_kernel(const float* __restrict__ A, const __nv_bfloat16* __restrict__ Bh,
                     const __nv_bfloat16* __restrict__ Bl, const float* __restrict__ bias,
                     float* __restrict__ C, const int* __restrict__ order, int Ntot)
{
    extern __shared__ char sm[];
    const uint32_t sb = smem_u32(sm);
    const int tid = threadIdx.x, wid = tid >> 5, lane = tid & 31;
    const int n0 = blockIdx.x * 128, m0 = blockIdx.y * 128;
    float* bias_s = (float*)sm;
    int*   rowidx = (int*)(sm + 512);

    if (tid < 128) {
        rowidx[tid] = (GATHER || SCATTER) ? order[m0 + tid] : (m0 + tid);
        bias_s[tid] = bias[n0 + tid];
    }
    __syncthreads();

    int aR[4], aU[4], bW[4], bR[4], bU[4];
    #pragma unroll
    for (int i = 0; i < 4; i++) {
        int idx = tid + i * 256;
        aR[i] = idx >> 3;  aU[i] = idx & 7;
        bW[i] = idx >> 9;  bR[i] = (idx >> 2) & 127;
        bU[i] = idx & 3;
    }

    const int wm = (wid & 1) * 64;
    const int wn = (wid >> 1) * 32;

    float acc[4][4][4];
    #pragma unroll
    for (int nt = 0; nt < 4; nt++) {
        float b0 = bias_s[wn + nt * 8 + 2 * (lane & 3)];
        float b1 = bias_s[wn + nt * 8 + 2 * (lane & 3) + 1];
        #pragma unroll
        for (int mt = 0; mt < 4; mt++) {
            acc[mt][nt][0] = b0; acc[mt][nt][1] = b1;
            acc[mt][nt][2] = b0; acc[mt][nt][3] = b1;
        }
    }

    float4 areg[4];
    uint4  breg[4];

    auto load_regs = [&](int k0) {
        #pragma unroll
        for (int i = 0; i < 4; i++) {
            int grow = GATHER ? rowidx[aR[i]] : (m0 + aR[i]);
            areg[i] = *(const float4*)(A + (size_t)grow * CC + k0 + aU[i] * 4);
        }
        #pragma unroll
        for (int i = 0; i < 4; i++) {
            const __nv_bfloat16* src =
                (bW[i] ? Bl : Bh) + (size_t)(n0 + bR[i]) * CC + k0 + bU[i] * 8;
            breg[i] = *(const uint4*)src;
        }
    };
    auto store_smem = [&](int stage) {
        char* base = sm + SM_TILES + stage * STAGEB;
        #pragma unroll
        for (int i = 0; i < 4; i++) {
            float4 v = areg[i];
            __nv_bfloat162 h01 = __floats2bfloat162_rn(v.x, v.y);
            __nv_bfloat162 h23 = __floats2bfloat162_rn(v.z, v.w);
            __nv_bfloat162 l01 = __floats2bfloat162_rn(v.x - __low2float(h01),
                                                       v.y - __high2float(h01));
            __nv_bfloat162 l23 = __floats2bfloat162_rn(v.z - __low2float(h23),
                                                       v.w - __high2float(h23));
            int off = aR[i] * ASTRIDE + aU[i] * 8;
            *(uint2*)(base + off) = make_uint2(*(uint32_t*)&h01, *(uint32_t*)&h23);
            *(uint2*)(base + TILEB + off) = make_uint2(*(uint32_t*)&l01, *(uint32_t*)&l23);
        }
        #pragma unroll
        for (int i = 0; i < 4; i++) {
            int off = 2 * TILEB + bW[i] * TILEB + bR[i] * ASTRIDE + bU[i] * 16;
            *(uint4*)(base + off) = breg[i];
        }
    };

    load_regs(0);
    store_smem(0);
    __syncthreads();

    const uint32_t a_lm = sb + SM_TILES + (wm + (lane & 15)) * ASTRIDE + ((lane >> 4) & 1) * 16;
    const uint32_t b_lm = sb + SM_TILES + 2 * TILEB + (wn + (lane & 7)) * ASTRIDE
                          + ((lane >> 3) & 1) * 16;

    const int NC = CC / 32;
    #pragma unroll 1
    for (int c = 0; c < NC; c++) {
        if (c + 1 < NC) load_regs((c + 1) * 32);
        const uint32_t abase = a_lm + (c & 1) * STAGEB;
        const uint32_t bbase = b_lm + (c & 1) * STAGEB;
        #pragma unroll
        for (int ks = 0; ks < 2; ks++) {
            const int ko = ks * 32;
            uint32_t ah[4][4], al[4][4], bh[4][2], bl[4][2];
            #pragma unroll
            for (int mt = 0; mt < 4; mt++) {
                ldsm_x4(ah[mt], abase + mt * 16 * ASTRIDE + ko);
                ldsm_x4(al[mt], abase + TILEB + mt * 16 * ASTRIDE + ko);
            }
            #pragma unroll
            for (int nt = 0; nt < 4; nt++) {
                ldsm_x2(bh[nt], bbase + nt * 8 * ASTRIDE + ko);
                ldsm_x2(bl[nt], bbase + TILEB + nt * 8 * ASTRIDE + ko);
            }
            #pragma unroll
            for (int mt = 0; mt < 4; mt++)
                #pragma unroll
                for (int nt = 0; nt < 4; nt++) {
                    mma_bf16(acc[mt][nt], ah[mt], bh[nt]);
                    mma_bf16(acc[mt][nt], ah[mt], bl[nt]);
                    mma_bf16(acc[mt][nt], al[mt], bh[nt]);
                }
        }
        __syncthreads();
        if (c + 1 < NC) {
            store_smem((c + 1) & 1);
            __syncthreads();
        }
    }

    #pragma unroll
    for (int mt = 0; mt < 4; mt++) {
        int lrow = wm + mt * 16 + (lane >> 2);
        int d0 = SCATTER ? rowidx[lrow]     : (m0 + lrow);
        int d1 = SCATTER ? rowidx[lrow + 8] : (m0 + lrow + 8);
        #pragma unroll
        for (int nt = 0; nt < 4; nt++) {
            int col = n0 + wn + nt * 8 + 2 * (lane & 3);
            *(float2*)(C + (size_t)d0 * Ntot + col) =
                make_float2(acc[mt][nt][0], acc[mt][nt][1]);
            *(float2*)(C + (size_t)d1 * Ntot + col) =
                make_float2(acc[mt][nt][2], acc[mt][nt][3]);
        }
    }
}

// ---------------- cls qkv ----------------
__global__ __launch_bounds__(128)
void cls_qkv_kernel(const float* __restrict__ cls_tokens,
                    const float* __restrict__ Wqkv,
                    const float* __restrict__ bqkv)
{
    __shared__ float ct[BB * CC];
    for (int i = threadIdx.x; i < BB * CC; i += 128) ct[i] = cls_tokens[i];
    __syncthreads();
    int n = blockIdx.x * 128 + threadIdx.x;
    float acc[BB];
    #pragma unroll
    for (int b = 0; b < BB; b++) acc[b] = bqkv[n];
    for (int k = 0; k < CC; k++) {
        float w = Wqkv[(size_t)k * C3 + n];
        #pragma unroll
        for (int b = 0; b < BB; b++) acc[b] += ct[b * CC + k] * w;
    }
    #pragma unroll
    for (int b = 0; b < BB; b++) g_clsqkv[b * C3 + n] = acc[b];
}

// ---------------- tensor-core attention (token queries tau=1..256) ----------------
// one CTA per (chunk, head); K/V bf16 hi/lo in smem, rows padded to 144B
#define NP 272
#define KROWB 144
#define ATT_SMEM (4 * NP * KROWB)   // 156672

__global__ __launch_bounds__(256)
void attn_mma_kernel(const int* __restrict__ offset)
{
    extern __shared__ char sm[];
    char* KhB = sm;
    char* KlB = sm + NP * KROWB;
    char* VhB = sm + 2 * NP * KROWB;
    char* VlB = sm + 3 * NP * KROWB;
    const uint32_t sb = smem_u32(sm);
    const uint32_t KhU = sb, KlU = sb + NP * KROWB;
    const uint32_t VhU = sb + 2 * NP * KROWB, VlU = sb + 3 * NP * KROWB;

    const int ci = blockIdx.x, h = blockIdx.y, tid = threadIdx.x;
    const int wid = tid >> 5, lane = tid & 31;
    const int cs = ci * KK;
    int b = 0;
    #pragma unroll
    for (int j = 0; j < BB; j++) b += (offset[j] <= cs) ? 1 : 0;
    const float* qkvbase = g_qkv + (size_t)cs * C3;
    const float* clsrow  = g_clsqkv + b * C3;
    const int koff = CC + h * DH, voff = 2 * CC + h * DH;

    // ---- load K,V -> smem bf16 hi/lo ----
    for (int idx = tid; idx < 2 * NP * 16; idx += 256) {
        int kv = idx >= NP * 16;
        int i  = kv ? idx - NP * 16 : idx;
        int t = i >> 4, d4 = (i & 15) << 2;
        int off = kv ? voff : koff;
        float4 v = make_float4(0.f, 0.f, 0.f, 0.f);
        if (t == 0)       v = *(const float4*)(clsrow + off + d4);
        else if (t <= KK) v = *(const float4*)(qkvbase + (size_t)(t - 1) * C3 + off + d4);
        __nv_bfloat162 h01 = __floats2bfloat162_rn(v.x, v.y);
        __nv_bfloat162 h23 = __floats2bfloat162_rn(v.z, v.w);
        __nv_bfloat162 l01 = __floats2bfloat162_rn(v.x - __low2float(h01),
                                                   v.y - __high2float(h01));
        __nv_bfloat162 l23 = __floats2bfloat162_rn(v.z - __low2float(h23),
                                                   v.w - __high2float(h23));
        char* hB = (kv ? VhB : KhB) + t * KROWB + d4 * 2;
        char* lB = (kv ? VlB : KlB) + t * KROWB + d4 * 2;
        *(uint2*)hB = make_uint2(*(uint32_t*)&h01, *(uint32_t*)&h23);
        *(uint2*)lB = make_uint2(*(uint32_t*)&l01, *(uint32_t*)&l23);
    }
    __syncthreads();

    const int r0 = lane >> 2;          // 0..7
    const int qp = (lane & 3) * 2;     // col pair base

    #pragma unroll 1
    for (int mt = wid; mt < 16; mt += 8) {
        const float* p0 = qkvbase + (size_t)(mt * 16 + r0) * C3 + h * DH;  // tau0-1
        const float* p1 = p0 + 8 * C3;

        float acc[34][4];
        #pragma unroll
        for (int nt = 0; nt < 34; nt++)
            acc[nt][0] = acc[nt][1] = acc[nt][2] = acc[nt][3] = 0.f;

        // ---- S = Q K^T (3-term split) ----
        #pragma unroll
        for (int kt = 0; kt < 4; kt++) {
            float2 q00 = *(const float2*)(p0 + kt * 16 + qp);
            float2 q10 = *(const float2*)(p1 + kt * 16 + qp);
            float2 q01 = *(const float2*)(p0 + kt * 16 + qp + 8);
            float2 q11 = *(const float2*)(p1 + kt * 16 + qp + 8);
            uint32_t qh[4], ql[4];
            qh[0] = split_pack(q00.x * 0.125f, q00.y * 0.125f, &ql[0]);
            qh[1] = split_pack(q10.x * 0.125f, q10.y * 0.125f, &ql[1]);
            qh[2] = split_pack(q01.x * 0.125f, q01.y * 0.125f, &ql[2]);
            qh[3] = split_pack(q11.x * 0.125f, q11.y * 0.125f, &ql[3]);
            const uint32_t kaddr = KhU + (lane & 7) * KROWB + ((lane >> 3) & 1) * 16 + kt * 32;
            #pragma unroll
            for (int nt = 0; nt < 34; nt++) {
                uint32_t bh[2], bl[2];
                ldsm_x2(bh, kaddr + nt * 8 * KROWB);
                ldsm_x2(bl, kaddr + NP * KROWB + nt * 8 * KROWB);
                mma_bf16(acc[nt], qh, bh);
                mma_bf16(acc[nt], qh, bl);
                mma_bf16(acc[nt], ql, bh);
            }
        }

        // ---- mask invalid key columns (col > 256) ----
        if (qp != 0) { acc[32][0] = -1e30f; acc[32][2] = -1e30f; }
        acc[32][1] = -1e30f; acc[32][3] = -1e30f;
        acc[33][0] = acc[33][1] = acc[33][2] = acc[33][3] = -1e30f;

        // ---- softmax (rows r0, r0+8) ----
        float m0 = -1e30f, m1 = -1e30f;
        #pragma unroll
        for (int nt = 0; nt < 34; nt++) {
            m0 = fmaxf(m0, fmaxf(acc[nt][0], acc[nt][1]));
            m1 = fmaxf(m1, fmaxf(acc[nt][2], acc[nt][3]));
        }
        m0 = fmaxf(m0, __shfl_xor_sync(0xffffffffu, m0, 1));
        m0 = fmaxf(m0, __shfl_xor_sync(0xffffffffu, m0, 2));
        m1 = fmaxf(m1, __shfl_xor_sync(0xffffffffu, m1, 1));
        m1 = fmaxf(m1, __shfl_xor_sync(0xffffffffu, m1, 2));
        float s0 = 0.f, s1 = 0.f;
        #pragma unroll
        for (int nt = 0; nt < 34; nt++) {
            acc[nt][0] = __expf(acc[nt][0] - m0);
            acc[nt][1] = __expf(acc[nt][1] - m0);
            acc[nt][2] = __expf(acc[nt][2] - m1);
            acc[nt][3] = __expf(acc[nt][3] - m1);
            s0 += acc[nt][0] + acc[nt][1];
            s1 += acc[nt][2] + acc[nt][3];
        }
        s0 += __shfl_xor_sync(0xffffffffu, s0, 1);
        s0 += __shfl_xor_sync(0xffffffffu, s0, 2);
        s1 += __shfl_xor_sync(0xffffffffu, s1, 1);
        s1 += __shfl_xor_sync(0xffffffffu, s1, 2);
        const float inv0 = 1.f / s0, inv1 = 1.f / s1;

        // ---- O = P V (3-term split, P from registers) ----
        float o[8][4];
        #pragma unroll
        for (int nt = 0; nt < 8; nt++)
            o[nt][0] = o[nt][1] = o[nt][2] = o[nt][3] = 0.f;

        #pragma unroll
        for (int kt = 0; kt < 17; kt++) {
            uint32_t ah[4], al[4];
            ah[0] = split_pack(acc[2*kt][0] * inv0,   acc[2*kt][1] * inv0,   &al[0]);
            ah[1] = split_pack(acc[2*kt][2] * inv1,   acc[2*kt][3] * inv1,   &al[1]);
            ah[2] = split_pack(acc[2*kt+1][0] * inv0, acc[2*kt+1][1] * inv0, &al[2]);
            ah[3] = split_pack(acc[2*kt+1][2] * inv1, acc[2*kt+1][3] * inv1, &al[3]);
            const uint32_t vaddr = VhU + (kt * 16 + (lane & 15)) * KROWB;
            #pragma unroll
            for (int nt = 0; nt < 8; nt++) {
                uint32_t bh[2], bl[2];
                ldsm_x2_t(bh, vaddr + nt * 16);
                ldsm_x2_t(bl, vaddr + NP * KROWB + nt * 16);
                mma_bf16(o[nt], ah, bh);
                mma_bf16(o[nt], ah, bl);
                mma_bf16(o[nt], al, bh);
            }
        }

        // ---- store ----
        float* d0 = g_att + (size_t)(cs + mt * 16 + r0) * CC + h * DH;
        float* d1 = d0 + 8 * CC;
        #pragma unroll
        for (int nt = 0; nt < 8; nt++) {
            *(float2*)(d0 + nt * 8 + qp) = make_float2(o[nt][0], o[nt][1]);
            *(float2*)(d1 + nt * 8 + qp) = make_float2(o[nt][2], o[nt][3]);
        }
    }
}

// ---------------- cls-query attention (tau=0 row), one warp per (chunk, head) ----------------
__global__ __launch_bounds__(256)
void cls_attn_kernel(const int* __restrict__ offset)
{
    __shared__ float sS[HH][257];
    const int ci = blockIdx.x, tid = threadIdx.x;
    const int h = tid >> 5, lane = tid & 31;
    const int cs = ci * KK;
    int b = 0;
    #pragma unroll
    for (int j = 0; j < BB; j++) b += (offset[j] <= cs) ? 1 : 0;
    const float* qkvbase = g_qkv + (size_t)cs * C3;
    const float* clsrow  = g_clsqkv + b * C3;
    const int koff = CC + h * DH, voff = 2 * CC + h * DH;

    const float q0 = clsrow[h * DH + lane] * 0.125f;
    const float q1 = clsrow[h * DH + lane + 32] * 0.125f;

    for (int j = 0; j < 257; j++) {
        const float* kr = (j == 0) ? (clsrow + koff)
                                   : (qkvbase + (size_t)(j - 1) * C3 + koff);
        float part = q0 * kr[lane] + q1 * kr[lane + 32];
        #pragma unroll
        for (int o = 16; o; o >>= 1) part += __shfl_xor_sync(0xffffffffu, part, o);
        if (lane == 0) sS[h][j] = part;
    }
    __syncwarp();

    float m = -1e30f;
    for (int j = lane; j < 257; j += 32) m = fmaxf(m, sS[h][j]);
    #pragma unroll
    for (int o = 16; o; o >>= 1) m = fmaxf(m, __shfl_xor_sync(0xffffffffu, m, o));
    float s = 0.f;
    for (int j = lane; j < 257; j += 32) {
        float e = __expf(sS[h][j] - m);
        sS[h][j] = e;
        s += e;
    }
    #pragma unroll
    for (int o = 16; o; o >>= 1) s += __shfl_xor_sync(0xffffffffu, s, o);
    const float inv = 1.f / s;
    __syncwarp();

    float o0 = 0.f, o1 = 0.f;
    for (int j = 0; j < 257; j++) {
        const float* vr = (j == 0) ? (clsrow + voff)
                                   : (qkvbase + (size_t)(j - 1) * C3 + voff);
        float p = sS[h][j] * inv;
        o0 += p * vr[lane];
        o1 += p * vr[lane + 32];
    }
    g_clspart[ci * CC + h * DH + lane]      = o0;
    g_clspart[ci * CC + h * DH + lane + 32] = o1;
}

// ---------------- cls reduce ----------------
__global__ __launch_bounds__(256)
void cls_reduce_kernel(const int* __restrict__ offset, float* __restrict__ out_cls)
{
    int gid = blockIdx.x * 256 + threadIdx.x;
    int b = gid >> 9;
    int c = gid & (CC - 1);
    int start = (b == 0) ? 0 : offset[b - 1];
    int end = offset[b];
    int ch0 = start / KK, ch1 = end / KK;
    float s = 0.f;
    for (int ch = ch0; ch < ch1; ch++) s += g_clspart[ch * CC + c];
    out_cls[gid] = s / (float)(ch1 - ch0);
}

// ---------------- launch ----------------
extern "C" void kernel_launch(void* const* d_in, const int* in_sizes, int n_in,
                              void* d_out, int out_size)
{
    const float* feat       = (const float*)d_in[0];
    const float* cls_tokens = (const float*)d_in[1];
    const float* Wqkv       = (const float*)d_in[2];
    const float* bqkv       = (const float*)d_in[3];
    const float* Wproj      = (const float*)d_in[4];
    const float* bproj      = (const float*)d_in[5];
    const int*   order      = (const int*)d_in[6];
    const int*   offset     = (const int*)d_in[8];

    float* out_feat = (float*)d_out;
    float* out_cls  = out_feat + (size_t)NPTS * CC;

    void *qkvp = nullptr, *attp = nullptr;
    void *wqh = nullptr, *wql = nullptr, *wph = nullptr, *wpl = nullptr;
    cudaGetSymbolAddress(&qkvp, g_qkv);
    cudaGetSymbolAddress(&attp, g_att);
    cudaGetSymbolAddress(&wqh, g_WqkvT_h);
    cudaGetSymbolAddress(&wql, g_WqkvT_l);
    cudaGetSymbolAddress(&wph, g_WprojT_h);
    cudaGetSymbolAddress(&wpl, g_WprojT_l);

    cudaFuncSetAttribute(attn_mma_kernel, cudaFuncAttributeMaxDynamicSharedMemorySize,
                         ATT_SMEM);
    cudaFuncSetAttribute(mma_gemm_kernel<true, false>,
                         cudaFuncAttributeMaxDynamicSharedMemorySize, GSMEM);
    cudaFuncSetAttribute(mma_gemm_kernel<false, true>,
                         cudaFuncAttributeMaxDynamicSharedMemorySize, GSMEM);

    // 0. transpose + bf16-split weights
    conv_wt_kernel<<<dim3(C3 / 32, CC / 32), 256>>>(
        Wqkv, (__nv_bfloat16*)wqh, (__nv_bfloat16*)wql, CC, C3);
    conv_wt_kernel<<<dim3(CC / 32, CC / 32), 256>>>(
        Wproj, (__nv_bfloat16*)wph, (__nv_bfloat16*)wpl, CC, CC);
    // 1. cls token qkv
    cls_qkv_kernel<<<C3 / 128, 128>>>(cls_tokens, Wqkv, bqkv);
    // 2. gathered qkv GEMM (mma.sync)
    mma_gemm_kernel<true, false><<<dim3(C3 / 128, NPTS / 128), 256, GSMEM>>>(
        feat, (const __nv_bfloat16*)wqh, (const __nv_bfloat16*)wql,
        bqkv, (float*)qkvp, order, C3);
    // 3. attention: token queries (tensor cores) + cls query (SIMT)
    attn_mma_kernel<<<dim3(NCH, HH), 256, ATT_SMEM>>>(offset);
    cls_attn_kernel<<<NCH, 256>>>(offset);
    // 4. proj GEMM (mma.sync) with scatter
    mma_gemm_kernel<false, true><<<dim3(CC / 128, NPTS / 128), 256, GSMEM>>>(
        (const float*)attp, (const __nv_bfloat16*)wph, (const __nv_bfloat16*)wpl,
        bproj, out_feat, order, CC);
    // 5. cls reduction
    cls_reduce_kernel<<<(BB * CC) / 256, 256>>>(offset, out_cls);
}

// round 5
// speedup vs baseline: 2.6685x; 1.0099x over previous
#include <cuda_runtime.h>
#include <cuda_bf16.h>
#include <cstdint>
#include <cstddef>

#define NPTS 65536
#define BB 4
#define CC 512
#define C3 1536
#define KK 256
#define HH 8
#define DH 64
#define NCH 256   // NPTS/KK

// ---------------- scratch (static device globals; no allocation) ----------------
__device__ float g_qkv[(size_t)NPTS * C3];     // gathered qkv, serialized order (fp32)
__device__ float g_clsqkv[BB * C3];            // cls token qkv
__device__ float g_clspart[NCH * CC];          // per-chunk cls attention row
__device__ __nv_bfloat16 g_Ah[(size_t)NPTS * CC];    // gathered feat hi
__device__ __nv_bfloat16 g_Al[(size_t)NPTS * CC];    // gathered feat lo
__device__ __nv_bfloat16 g_att_h[(size_t)NPTS * CC]; // attention out hi (serialized)
__device__ __nv_bfloat16 g_att_l[(size_t)NPTS * CC]; // attention out lo
__device__ __nv_bfloat16 g_WqkvT_h[(size_t)C3 * CC];
__device__ __nv_bfloat16 g_WqkvT_l[(size_t)C3 * CC];
__device__ __nv_bfloat16 g_WprojT_h[(size_t)CC * CC];
__device__ __nv_bfloat16 g_WprojT_l[(size_t)CC * CC];

// =============== helpers ===============
__device__ __forceinline__ uint32_t smem_u32(const void* p) {
    uint32_t a;
    asm("{ .reg .u64 t; cvta.to.shared.u64 t, %1; cvt.u32.u64 %0, t; }" : "=r"(a) : "l"(p));
    return a;
}
__device__ __forceinline__ void ldsm_x4(uint32_t* r, uint32_t addr) {
    asm volatile("ldmatrix.sync.aligned.m8n8.x4.shared.b16 {%0,%1,%2,%3}, [%4];"
                 : "=r"(r[0]), "=r"(r[1]), "=r"(r[2]), "=r"(r[3]) : "r"(addr));
}
__device__ __forceinline__ void ldsm_x2(uint32_t* r, uint32_t addr) {
    asm volatile("ldmatrix.sync.aligned.m8n8.x2.shared.b16 {%0,%1}, [%2];"
                 : "=r"(r[0]), "=r"(r[1]) : "r"(addr));
}
__device__ __forceinline__ void ldsm_x2_t(uint32_t* r, uint32_t addr) {
    asm volatile("ldmatrix.sync.aligned.m8n8.x2.trans.shared.b16 {%0,%1}, [%2];"
                 : "=r"(r[0]), "=r"(r[1]) : "r"(addr));
}
__device__ __forceinline__ void mma_bf16(float* c, const uint32_t* a, const uint32_t* b) {
    asm volatile(
        "mma.sync.aligned.m16n8k16.row.col.f32.bf16.bf16.f32 "
        "{%0,%1,%2,%3}, {%4,%5,%6,%7}, {%8,%9}, {%0,%1,%2,%3};"
        : "+f"(c[0]), "+f"(c[1]), "+f"(c[2]), "+f"(c[3])
        : "r"(a[0]), "r"(a[1]), "r"(a[2]), "r"(a[3]), "r"(b[0]), "r"(b[1]));
}
__device__ __forceinline__ uint32_t split_pack(float x, float y, uint32_t* lo) {
    __nv_bfloat162 hh = __floats2bfloat162_rn(x, y);
    __nv_bfloat162 ll = __floats2bfloat162_rn(x - __low2float(hh), y - __high2float(hh));
    *lo = *reinterpret_cast<uint32_t*>(&ll);
    return *reinterpret_cast<uint32_t*>(&hh);
}
__device__ __forceinline__ void cp_async16(uint32_t dst, const void* src) {
    asm volatile("cp.async.cg.shared.global [%0], [%1], 16;" :: "r"(dst), "l"(src) : "memory");
}
#define CP_COMMIT() asm volatile("cp.async.commit_group;" ::: "memory")
#define CP_WAIT1()  asm volatile("cp.async.wait_group 1;" ::: "memory")

// ---------------- W transpose + bf16 split: W[K,N] fp32 -> T[N,K] hi/lo ----------------
__global__ __launch_bounds__(256)
void conv_wt_kernel(const float* __restrict__ W, __nv_bfloat16* __restrict__ Th,
                    __nv_bfloat16* __restrict__ Tl, int K, int N)
{
    __shared__ float t[32][33];
    int n0 = blockIdx.x * 32, k0 = blockIdx.y * 32;
    int tx = threadIdx.x & 31, ty = threadIdx.x >> 5;
    #pragma unroll
    for (int j = 0; j < 32; j += 8)
        t[ty + j][tx] = W[(size_t)(k0 + ty + j) * N + n0 + tx];
    __syncthreads();
    #pragma unroll
    for (int j = 0; j < 32; j += 8) {
        int n = n0 + ty + j, k = k0 + tx;
        float v = t[tx][ty + j];
        __nv_bfloat16 h = __float2bfloat16(v);
        __nv_bfloat16 l = __float2bfloat16(v - __bfloat162float(h));
        Th[(size_t)n * K + k] = h;
        Tl[(size_t)n * K + k] = l;
    }
}

// ---------------- feat gather + bf16 split ----------------
__global__ __launch_bounds__(256)
void conv_feat_kernel(const float* __restrict__ feat, const int* __restrict__ order)
{
    size_t idx = (size_t)blockIdx.x * 256 + threadIdx.x;   // over NPTS*CC/4
    int m = (int)(idx >> 7);         // CC/4 = 128 float4 per row
    int u = (int)(idx & 127);
    const float4 v = *(const float4*)(feat + (size_t)order[m] * CC + u * 4);
    __nv_bfloat162 h01 = __floats2bfloat162_rn(v.x, v.y);
    __nv_bfloat162 h23 = __floats2bfloat162_rn(v.z, v.w);
    __nv_bfloat162 l01 = __floats2bfloat162_rn(v.x - __low2float(h01), v.y - __high2float(h01));
    __nv_bfloat162 l23 = __floats2bfloat162_rn(v.z - __low2float(h23), v.w - __high2float(h23));
    *(uint2*)(g_Ah + (size_t)m * CC + u * 4) =
        make_uint2(*(uint32_t*)&h01, *(uint32_t*)&h23);
    *(uint2*)(g_Al + (size_t)m * CC + u * 4) =
        make_uint2(*(uint32_t*)&l01, *(uint32_t*)&l23);
}

// ---------------- cp.async pipelined GEMM: 128x128 tile, Kc=32, 3 stages ----------------
#define PROWB  80
#define PTILE  (128 * PROWB)     // 10240
#define PSTAGE (4 * PTILE)       // 40960
#define GSMEM  (1024 + 3 * PSTAGE)   // 123904

template<bool SCATTER>
__global__ __launch_bounds__(256)
void gemm_async_kernel(const __nv_bfloat16* __restrict__ Ah, const __nv_bfloat16* __restrict__ Al,
                       const __nv_bfloat16* __restrict__ Bh, const __nv_bfloat16* __restrict__ Bl,
                       const float* __restrict__ bias, float* __restrict__ C,
                       const int* __restrict__ order, int Ntot)
{
    extern __shared__ char sm[];
    const uint32_t sb = smem_u32(sm);
    const int tid = threadIdx.x, wid = tid >> 5, lane = tid & 31;
    const int n0 = blockIdx.x * 128, m0 = blockIdx.y * 128;
    float* bias_s = (float*)sm;
    int*   rowidx = (int*)(sm + 512);

    const int cr = tid >> 2;        // 0..63
    const int cu = (tid & 3) * 16;  // byte offset within 64B row

    auto issue_stage = [&](int c, int stage) {
        const int k0 = c * 32;
        const uint32_t dbase = sb + 1024 + stage * PSTAGE;
        #pragma unroll
        for (int i = 0; i < 8; i++) {
            const int tile = i >> 1;
            const int r = (i & 1) * 64 + cr;
            const uint32_t dst = dbase + tile * PTILE + r * PROWB + cu;
            const __nv_bfloat16* src;
            if (tile == 0)      src = Ah + (size_t)(m0 + r) * CC + k0;
            else if (tile == 1) src = Al + (size_t)(m0 + r) * CC + k0;
            else if (tile == 2) src = Bh + (size_t)(n0 + r) * CC + k0;
            else                src = Bl + (size_t)(n0 + r) * CC + k0;
            cp_async16(dst, (const char*)src + cu);
        }
    };

    issue_stage(0, 0); CP_COMMIT();
    issue_stage(1, 1); CP_COMMIT();

    if (tid < 128) {
        bias_s[tid] = bias[n0 + tid];
        if (SCATTER) rowidx[tid] = order[m0 + tid];
    }
    __syncthreads();

    const int wm = (wid & 1) * 64;
    const int wn = (wid >> 1) * 32;

    float acc[4][4][4];
    #pragma unroll
    for (int nt = 0; nt < 4; nt++) {
        float b0 = bias_s[wn + nt * 8 + 2 * (lane & 3)];
        float b1 = bias_s[wn + nt * 8 + 2 * (lane & 3) + 1];
        #pragma unroll
        for (int mt = 0; mt < 4; mt++) {
            acc[mt][nt][0] = b0; acc[mt][nt][1] = b1;
            acc[mt][nt][2] = b0; acc[mt][nt][3] = b1;
        }
    }

    const uint32_t a_lm = sb + 1024 + (wm + (lane & 15)) * PROWB + ((lane >> 4) & 1) * 16;
    const uint32_t b_lm = sb + 1024 + 2 * PTILE + (wn + (lane & 7)) * PROWB
                          + ((lane >> 3) & 1) * 16;

    const int NC = CC / 32;   // 16
    #pragma unroll 1
    for (int c = 0; c < NC; c++) {
        CP_WAIT1();
        __syncthreads();
        if (c + 2 < NC) issue_stage(c + 2, (c + 2) % 3);
        CP_COMMIT();

        const uint32_t abase = a_lm + (c % 3) * PSTAGE;
        const uint32_t bbase = b_lm + (c % 3) * PSTAGE;
        #pragma unroll
        for (int ks = 0; ks < 2; ks++) {
            const int ko = ks * 32;
            uint32_t ah[4][4], al[4][4], bh[4][2], bl[4][2];
            #pragma unroll
            for (int mt = 0; mt < 4; mt++) {
                ldsm_x4(ah[mt], abase + mt * 16 * PROWB + ko);
                ldsm_x4(al[mt], abase + PTILE + mt * 16 * PROWB + ko);
            }
            #pragma unroll
            for (int nt = 0; nt < 4; nt++) {
                ldsm_x2(bh[nt], bbase + nt * 8 * PROWB + ko);
                ldsm_x2(bl[nt], bbase + PTILE + nt * 8 * PROWB + ko);
            }
            #pragma unroll
            for (int mt = 0; mt < 4; mt++)
                #pragma unroll
                for (int nt = 0; nt < 4; nt++) {
                    mma_bf16(acc[mt][nt], ah[mt], bh[nt]);
                    mma_bf16(acc[mt][nt], ah[mt], bl[nt]);
                    mma_bf16(acc[mt][nt], al[mt], bh[nt]);
                }
        }
    }

    #pragma unroll
    for (int mt = 0; mt < 4; mt++) {
        int lrow = wm + mt * 16 + (lane >> 2);
        int d0 = SCATTER ? rowidx[lrow]     : (m0 + lrow);
        int d1 = SCATTER ? rowidx[lrow + 8] : (m0 + lrow + 8);
        #pragma unroll
        for (int nt = 0; nt < 4; nt++) {
            int col = n0 + wn + nt * 8 + 2 * (lane & 3);
            *(float2*)(C + (size_t)d0 * Ntot + col) =
                make_float2(acc[mt][nt][0], acc[mt][nt][1]);
            *(float2*)(C + (size_t)d1 * Ntot + col) =
                make_float2(acc[mt][nt][2], acc[mt][nt][3]);
        }
    }
}

// ---------------- cls qkv ----------------
__global__ __launch_bounds__(128)
void cls_qkv_kernel(const float* __restrict__ cls_tokens,
                    const float* __restrict__ Wqkv,
                    const float* __restrict__ bqkv)
{
    __shared__ float ct[BB * CC];
    for (int i = threadIdx.x; i < BB * CC; i += 128) ct[i] = cls_tokens[i];
    __syncthreads();
    int n = blockIdx.x * 128 + threadIdx.x;
    float acc[BB];
    #pragma unroll
    for (int b = 0; b < BB; b++) acc[b] = bqkv[n];
    for (int k = 0; k < CC; k++) {
        float w = Wqkv[(size_t)k * C3 + n];
        #pragma unroll
        for (int b = 0; b < BB; b++) acc[b] += ct[b * CC + k] * w;
    }
    #pragma unroll
    for (int b = 0; b < BB; b++) g_clsqkv[b * C3 + n] = acc[b];
}

// ---------------- tensor-core attention (token queries tau=1..256) ----------------
#define NP 272
#define KROWB 144
#define ATT_SMEM (4 * NP * KROWB)   // 156672

__global__ __launch_bounds__(256)
void attn_mma_kernel(const int* __restrict__ offset)
{
    extern __shared__ char sm[];
    char* KhB = sm;
    char* KlB = sm + NP * KROWB;
    char* VhB = sm + 2 * NP * KROWB;
    char* VlB = sm + 3 * NP * KROWB;
    const uint32_t sb = smem_u32(sm);
    const uint32_t KhU = sb;
    const uint32_t VhU = sb + 2 * NP * KROWB;

    const int ci = blockIdx.x, h = blockIdx.y, tid = threadIdx.x;
    const int wid = tid >> 5, lane = tid & 31;
    const int cs = ci * KK;
    int b = 0;
    #pragma unroll
    for (int j = 0; j < BB; j++) b += (offset[j] <= cs) ? 1 : 0;
    const float* qkvbase = g_qkv + (size_t)cs * C3;
    const float* clsrow  = g_clsqkv + b * C3;
    const int koff = CC + h * DH, voff = 2 * CC + h * DH;

    for (int idx = tid; idx < 2 * NP * 16; idx += 256) {
        int kv = idx >= NP * 16;
        int i  = kv ? idx - NP * 16 : idx;
        int t = i >> 4, d4 = (i & 15) << 2;
        int off = kv ? voff : koff;
        float4 v = make_float4(0.f, 0.f, 0.f, 0.f);
        if (t == 0)       v = *(const float4*)(clsrow + off + d4);
        else if (t <= KK) v = *(const float4*)(qkvbase + (size_t)(t - 1) * C3 + off + d4);
        __nv_bfloat162 h01 = __floats2bfloat162_rn(v.x, v.y);
        __nv_bfloat162 h23 = __floats2bfloat162_rn(v.z, v.w);
        __nv_bfloat162 l01 = __floats2bfloat162_rn(v.x - __low2float(h01),
                                                   v.y - __high2float(h01));
        __nv_bfloat162 l23 = __floats2bfloat162_rn(v.z - __low2float(h23),
                                                   v.w - __high2float(h23));
        char* hB = (kv ? VhB : KhB) + t * KROWB + d4 * 2;
        char* lB = (kv ? VlB : KlB) + t * KROWB + d4 * 2;
        *(uint2*)hB = make_uint2(*(uint32_t*)&h01, *(uint32_t*)&h23);
        *(uint2*)lB = make_uint2(*(uint32_t*)&l01, *(uint32_t*)&l23);
    }
    __syncthreads();

    const int r0 = lane >> 2;
    const int qp = (lane & 3) * 2;

    #pragma unroll 1
    for (int mt = wid; mt < 16; mt += 8) {
        const float* p0 = qkvbase + (size_t)(mt * 16 + r0) * C3 + h * DH;
        const float* p1 = p0 + 8 * C3;

        float acc[34][4];
        #pragma unroll
        for (int nt = 0; nt < 34; nt++)
            acc[nt][0] = acc[nt][1] = acc[nt][2] = acc[nt][3] = 0.f;

        #pragma unroll
        for (int kt = 0; kt < 4; kt++) {
            float2 q00 = *(const float2*)(p0 + kt * 16 + qp);
            float2 q10 = *(const float2*)(p1 + kt * 16 + qp);
            float2 q01 = *(const float2*)(p0 + kt * 16 + qp + 8);
            float2 q11 = *(const float2*)(p1 + kt * 16 + qp + 8);
            uint32_t qh[4], ql[4];
            qh[0] = split_pack(q00.x * 0.125f, q00.y * 0.125f, &ql[0]);
            qh[1] = split_pack(q10.x * 0.125f, q10.y * 0.125f, &ql[1]);
            qh[2] = split_pack(q01.x * 0.125f, q01.y * 0.125f, &ql[2]);
            qh[3] = split_pack(q11.x * 0.125f, q11.y * 0.125f, &ql[3]);
            const uint32_t kaddr = KhU + (lane & 7) * KROWB + ((lane >> 3) & 1) * 16 + kt * 32;
            #pragma unroll
            for (int nt = 0; nt < 34; nt++) {
                uint32_t bh[2], bl[2];
                ldsm_x2(bh, kaddr + nt * 8 * KROWB);
                ldsm_x2(bl, kaddr + NP * KROWB + nt * 8 * KROWB);
                mma_bf16(acc[nt], qh, bh);
                mma_bf16(acc[nt], qh, bl);
                mma_bf16(acc[nt], ql, bh);
            }
        }

        if (qp != 0) { acc[32][0] = -1e30f; acc[32][2] = -1e30f; }
        acc[32][1] = -1e30f; acc[32][3] = -1e30f;
        acc[33][0] = acc[33][1] = acc[33][2] = acc[33][3] = -1e30f;

        float m0 = -1e30f, m1 = -1e30f;
        #pragma unroll
        for (int nt = 0; nt < 34; nt++) {
            m0 = fmaxf(m0, fmaxf(acc[nt][0], acc[nt][1]));
            m1 = fmaxf(m1, fmaxf(acc[nt][2], acc[nt][3]));
        }
        m0 = fmaxf(m0, __shfl_xor_sync(0xffffffffu, m0, 1));
        m0 = fmaxf(m0, __shfl_xor_sync(0xffffffffu, m0, 2));
        m1 = fmaxf(m1, __shfl_xor_sync(0xffffffffu, m1, 1));
        m1 = fmaxf(m1, __shfl_xor_sync(0xffffffffu, m1, 2));
        float s0 = 0.f, s1 = 0.f;
        #pragma unroll
        for (int nt = 0; nt < 34; nt++) {
            acc[nt][0] = __expf(acc[nt][0] - m0);
            acc[nt][1] = __expf(acc[nt][1] - m0);
            acc[nt][2] = __expf(acc[nt][2] - m1);
            acc[nt][3] = __expf(acc[nt][3] - m1);
            s0 += acc[nt][0] + acc[nt][1];
            s1 += acc[nt][2] + acc[nt][3];
        }
        s0 += __shfl_xor_sync(0xffffffffu, s0, 1);
        s0 += __shfl_xor_sync(0xffffffffu, s0, 2);
        s1 += __shfl_xor_sync(0xffffffffu, s1, 1);
        s1 += __shfl_xor_sync(0xffffffffu, s1, 2);
        const float inv0 = 1.f / s0, inv1 = 1.f / s1;

        float o[8][4];
        #pragma unroll
        for (int nt = 0; nt < 8; nt++)
            o[nt][0] = o[nt][1] = o[nt][2] = o[nt][3] = 0.f;

        #pragma unroll
        for (int kt = 0; kt < 17; kt++) {
            uint32_t ah[4], al[4];
            ah[0] = split_pack(acc[2*kt][0] * inv0,   acc[2*kt][1] * inv0,   &al[0]);
            ah[1] = split_pack(acc[2*kt][2] * inv1,   acc[2*kt][3] * inv1,   &al[1]);
            ah[2] = split_pack(acc[2*kt+1][0] * inv0, acc[2*kt+1][1] * inv0, &al[2]);
            ah[3] = split_pack(acc[2*kt+1][2] * inv1, acc[2*kt+1][3] * inv1, &al[3]);
            const uint32_t vaddr = VhU + (kt * 16 + (lane & 15)) * KROWB;
            #pragma unroll
            for (int nt = 0; nt < 8; nt++) {
                uint32_t bh[2], bl[2];
                ldsm_x2_t(bh, vaddr + nt * 16);
                ldsm_x2_t(bl, vaddr + NP * KROWB + nt * 16);
                mma_bf16(o[nt], ah, bh);
                mma_bf16(o[nt], ah, bl);
                mma_bf16(o[nt], al, bh);
            }
        }

        // ---- store split bf16 hi/lo ----
        const size_t row0 = (size_t)(cs + mt * 16 + r0) * CC + h * DH;
        const size_t row1 = row0 + 8 * CC;
        #pragma unroll
        for (int nt = 0; nt < 8; nt++) {
            uint32_t lo;
            uint32_t hi = split_pack(o[nt][0], o[nt][1], &lo);
            *(uint32_t*)(g_att_h + row0 + nt * 8 + qp) = hi;
            *(uint32_t*)(g_att_l + row0 + nt * 8 + qp) = lo;
            hi = split_pack(o[nt][2], o[nt][3], &lo);
            *(uint32_t*)(g_att_h + row1 + nt * 8 + qp) = hi;
            *(uint32_t*)(g_att_l + row1 + nt * 8 + qp) = lo;
        }
    }
}

// ---------------- cls-query attention ----------------
__global__ __launch_bounds__(256)
void cls_attn_kernel(const int* __restrict__ offset)
{
    __shared__ float sS[HH][257];
    const int ci = blockIdx.x, tid = threadIdx.x;
    const int h = tid >> 5, lane = tid & 31;
    const int cs = ci * KK;
    int b = 0;
    #pragma unroll
    for (int j = 0; j < BB; j++) b += (offset[j] <= cs) ? 1 : 0;
    const float* qkvbase = g_qkv + (size_t)cs * C3;
    const float* clsrow  = g_clsqkv + b * C3;
    const int koff = CC + h * DH, voff = 2 * CC + h * DH;

    const float q0 = clsrow[h * DH + lane] * 0.125f;
    const float q1 = clsrow[h * DH + lane + 32] * 0.125f;

    for (int j = 0; j < 257; j++) {
        const float* kr = (j == 0) ? (clsrow + koff)
                                   : (qkvbase + (size_t)(j - 1) * C3 + koff);
        float part = q0 * kr[lane] + q1 * kr[lane + 32];
        #pragma unroll
        for (int o = 16; o; o >>= 1) part += __shfl_xor_sync(0xffffffffu, part, o);
        if (lane == 0) sS[h][j] = part;
    }
    __syncwarp();

    float m = -1e30f;
    for (int j = lane; j < 257; j += 32) m = fmaxf(m, sS[h][j]);
    #pragma unroll
    for (int o = 16; o; o >>= 1) m = fmaxf(m, __shfl_xor_sync(0xffffffffu, m, o));
    float s = 0.f;
    for (int j = lane; j < 257; j += 32) {
        float e = __expf(sS[h][j] - m);
        sS[h][j] = e;
        s += e;
    }
    #pragma unroll
    for (int o = 16; o; o >>= 1) s += __shfl_xor_sync(0xffffffffu, s, o);
    const float inv = 1.f / s;
    __syncwarp();

    float o0 = 0.f, o1 = 0.f;
    for (int j = 0; j < 257; j++) {
        const float* vr = (j == 0) ? (clsrow + voff)
                                   : (qkvbase + (size_t)(j - 1) * C3 + voff);
        float p = sS[h][j] * inv;
        o0 += p * vr[lane];
        o1 += p * vr[lane + 32];
    }
    g_clspart[ci * CC + h * DH + lane]      = o0;
    g_clspart[ci * CC + h * DH + lane + 32] = o1;
}

// ---------------- cls reduce ----------------
__global__ __launch_bounds__(256)
void cls_reduce_kernel(const int* __restrict__ offset, float* __restrict__ out_cls)
{
    int gid = blockIdx.x * 256 + threadIdx.x;
    int b = gid >> 9;
    int c = gid & (CC - 1);
    int start = (b == 0) ? 0 : offset[b - 1];
    int end = offset[b];
    int ch0 = start / KK, ch1 = end / KK;
    float s = 0.f;
    for (int ch = ch0; ch < ch1; ch++) s += g_clspart[ch * CC + c];
    out_cls[gid] = s / (float)(ch1 - ch0);
}

// ---------------- launch ----------------
extern "C" void kernel_launch(void* const* d_in, const int* in_sizes, int n_in,
                              void* d_out, int out_size)
{
    const float* feat       = (const float*)d_in[0];
    const float* cls_tokens = (const float*)d_in[1];
    const float* Wqkv       = (const float*)d_in[2];
    const float* bqkv       = (const float*)d_in[3];
    const float* Wproj      = (const float*)d_in[4];
    const float* bproj      = (const float*)d_in[5];
    const int*   order      = (const int*)d_in[6];
    const int*   offset     = (const int*)d_in[8];

    float* out_feat = (float*)d_out;
    float* out_cls  = out_feat + (size_t)NPTS * CC;

    void *qkvp = nullptr;
    void *ah = nullptr, *al = nullptr, *ath = nullptr, *atl = nullptr;
    void *wqh = nullptr, *wql = nullptr, *wph = nullptr, *wpl = nullptr;
    cudaGetSymbolAddress(&qkvp, g_qkv);
    cudaGetSymbolAddress(&ah, g_Ah);
    cudaGetSymbolAddress(&al, g_Al);
    cudaGetSymbolAddress(&ath, g_att_h);
    cudaGetSymbolAddress(&atl, g_att_l);
    cudaGetSymbolAddress(&wqh, g_WqkvT_h);
    cudaGetSymbolAddress(&wql, g_WqkvT_l);
    cudaGetSymbolAddress(&wph, g_WprojT_h);
    cudaGetSymbolAddress(&wpl, g_WprojT_l);

    cudaFuncSetAttribute(attn_mma_kernel, cudaFuncAttributeMaxDynamicSharedMemorySize,
                         ATT_SMEM);
    cudaFuncSetAttribute(gemm_async_kernel<false>,
                         cudaFuncAttributeMaxDynamicSharedMemorySize, GSMEM);
    cudaFuncSetAttribute(gemm_async_kernel<true>,
                         cudaFuncAttributeMaxDynamicSharedMemorySize, GSMEM);

    // 0. weight transpose+split, feat gather+split
    conv_wt_kernel<<<dim3(C3 / 32, CC / 32), 256>>>(
        Wqkv, (__nv_bfloat16*)wqh, (__nv_bfloat16*)wql, CC, C3);
    conv_wt_kernel<<<dim3(CC / 32, CC / 32), 256>>>(
        Wproj, (__nv_bfloat16*)wph, (__nv_bfloat16*)wpl, CC, CC);
    conv_feat_kernel<<<(NPTS * (CC / 4)) / 256, 256>>>(feat, order);
    // 1. cls token qkv
    cls_qkv_kernel<<<C3 / 128, 128>>>(cls_tokens, Wqkv, bqkv);
    // 2. qkv GEMM (cp.async + mma.sync)
    gemm_async_kernel<false><<<dim3(C3 / 128, NPTS / 128), 256, GSMEM>>>(
        (const __nv_bfloat16*)ah, (const __nv_bfloat16*)al,
        (const __nv_bfloat16*)wqh, (const __nv_bfloat16*)wql,
        bqkv, (float*)qkvp, order, C3);
    // 3. attention
    attn_mma_kernel<<<dim3(NCH, HH), 256, ATT_SMEM>>>(offset);
    cls_attn_kernel<<<NCH, 256>>>(offset);
    // 4. proj GEMM with scatter
    gemm_async_kernel<true><<<dim3(CC / 128, NPTS / 128), 256, GSMEM>>>(
        (const __nv_bfloat16*)ath, (const __nv_bfloat16*)atl,
        (const __nv_bfloat16*)wph, (const __nv_bfloat16*)wpl,
        bproj, out_feat, order, CC);
    // 5. cls reduction
    cls_reduce_kernel<<<(BB * CC) / 256, 256>>>(offset, out_cls);
}

// round 6
// speedup vs baseline: 3.7128x; 1.3913x over previous
#include <cuda_runtime.h>
#include <cuda_fp16.h>
#include <cstdint>
#include <cstddef>

#define NPTS 65536
#define BB 4
#define CC 512
#define C3 1536
#define KK 256
#define HH 8
#define DH 64
#define NCH 256   // NPTS/KK

// ---------------- scratch (static device globals; no allocation) ----------------
__device__ float g_qkv[(size_t)NPTS * C3];     // gathered qkv, serialized order (fp32)
__device__ float g_clsqkv[BB * C3];            // cls token qkv
__device__ float g_clspart[NCH * CC];          // per-chunk cls attention row
__device__ __half g_Ah[(size_t)NPTS * CC];     // gathered feat hi (fp16)
__device__ __half g_Al[(size_t)NPTS * CC];     // gathered feat lo
__device__ __half g_att_h[(size_t)NPTS * CC];  // attention out hi (serialized)
__device__ __half g_att_l[(size_t)NPTS * CC];  // attention out lo
__device__ __half g_WqkvT[(size_t)C3 * CC];    // W^T fp16 (hi only)
__device__ __half g_WprojT[(size_t)CC * CC];

// =============== helpers ===============
__device__ __forceinline__ uint32_t smem_u32(const void* p) {
    uint32_t a;
    asm("{ .reg .u64 t; cvta.to.shared.u64 t, %1; cvt.u32.u64 %0, t; }" : "=r"(a) : "l"(p));
    return a;
}
__device__ __forceinline__ void ldsm_x4(uint32_t* r, uint32_t addr) {
    asm volatile("ldmatrix.sync.aligned.m8n8.x4.shared.b16 {%0,%1,%2,%3}, [%4];"
                 : "=r"(r[0]), "=r"(r[1]), "=r"(r[2]), "=r"(r[3]) : "r"(addr));
}
__device__ __forceinline__ void ldsm_x2(uint32_t* r, uint32_t addr) {
    asm volatile("ldmatrix.sync.aligned.m8n8.x2.shared.b16 {%0,%1}, [%2];"
                 : "=r"(r[0]), "=r"(r[1]) : "r"(addr));
}
__device__ __forceinline__ void ldsm_x2_t(uint32_t* r, uint32_t addr) {
    asm volatile("ldmatrix.sync.aligned.m8n8.x2.trans.shared.b16 {%0,%1}, [%2];"
                 : "=r"(r[0]), "=r"(r[1]) : "r"(addr));
}
__device__ __forceinline__ void mma_f16(float* c, const uint32_t* a, const uint32_t* b) {
    asm volatile(
        "mma.sync.aligned.m16n8k16.row.col.f32.f16.f16.f32 "
        "{%0,%1,%2,%3}, {%4,%5,%6,%7}, {%8,%9}, {%0,%1,%2,%3};"
        : "+f"(c[0]), "+f"(c[1]), "+f"(c[2]), "+f"(c[3])
        : "r"(a[0]), "r"(a[1]), "r"(a[2]), "r"(a[3]), "r"(b[0]), "r"(b[1]));
}
// split two fp32 into fp16 hi pair (returned) + fp16 lo pair (via *lo)
__device__ __forceinline__ uint32_t split_pack_h(float x, float y, uint32_t* lo) {
    __half2 hh = __floats2half2_rn(x, y);
    __half2 ll = __floats2half2_rn(x - __low2float(hh), y - __high2float(hh));
    *lo = *reinterpret_cast<uint32_t*>(&ll);
    return *reinterpret_cast<uint32_t*>(&hh);
}
__device__ __forceinline__ void cp_async16(uint32_t dst, const void* src) {
    asm volatile("cp.async.cg.shared.global [%0], [%1], 16;" :: "r"(dst), "l"(src) : "memory");
}
#define CP_COMMIT() asm volatile("cp.async.commit_group;" ::: "memory")
#define CP_WAIT1()  asm volatile("cp.async.wait_group 1;" ::: "memory")

// ---------------- W transpose to fp16: W[K,N] fp32 -> T[N,K] fp16 ----------------
__global__ __launch_bounds__(256)
void conv_wt_kernel(const float* __restrict__ W, __half* __restrict__ T, int K, int N)
{
    __shared__ float t[32][33];
    int n0 = blockIdx.x * 32, k0 = blockIdx.y * 32;
    int tx = threadIdx.x & 31, ty = threadIdx.x >> 5;
    #pragma unroll
    for (int j = 0; j < 32; j += 8)
        t[ty + j][tx] = W[(size_t)(k0 + ty + j) * N + n0 + tx];
    __syncthreads();
    #pragma unroll
    for (int j = 0; j < 32; j += 8) {
        int n = n0 + ty + j, k = k0 + tx;
        T[(size_t)n * K + k] = __float2half_rn(t[tx][ty + j]);
    }
}

// ---------------- feat gather + fp16 split ----------------
__global__ __launch_bounds__(256)
void conv_feat_kernel(const float* __restrict__ feat, const int* __restrict__ order)
{
    size_t idx = (size_t)blockIdx.x * 256 + threadIdx.x;   // over NPTS*CC/4
    int m = (int)(idx >> 7);
    int u = (int)(idx & 127);
    const float4 v = *(const float4*)(feat + (size_t)order[m] * CC + u * 4);
    uint32_t l01, l23;
    uint32_t h01 = split_pack_h(v.x, v.y, &l01);
    uint32_t h23 = split_pack_h(v.z, v.w, &l23);
    *(uint2*)(g_Ah + (size_t)m * CC + u * 4) = make_uint2(h01, h23);
    *(uint2*)(g_Al + (size_t)m * CC + u * 4) = make_uint2(l01, l23);
}

// ---------------- cp.async pipelined GEMM: 128x128 tile, Kc=32, fp16 2-term ----------------
#define PROWB  80
#define PTILE  (128 * PROWB)     // 10240
#define PSTAGE (3 * PTILE)       // 30720 (Ah | Al | Bh)
#define GSMEM  (1024 + 3 * PSTAGE)   // 93184

template<bool SCATTER>
__global__ __launch_bounds__(256)
void gemm_async_kernel(const __half* __restrict__ Ah, const __half* __restrict__ Al,
                       const __half* __restrict__ Bh,
                       const float* __restrict__ bias, float* __restrict__ C,
                       const int* __restrict__ order, int Ntot)
{
    extern __shared__ char sm[];
    const uint32_t sb = smem_u32(sm);
    const int tid = threadIdx.x, wid = tid >> 5, lane = tid & 31;
    const int n0 = blockIdx.x * 128, m0 = blockIdx.y * 128;
    float* bias_s = (float*)sm;
    int*   rowidx = (int*)(sm + 512);

    const int cr = tid >> 2;        // 0..63
    const int cu = (tid & 3) * 16;  // byte offset within 64B row

    auto issue_stage = [&](int c, int stage) {
        const int k0 = c * 32;
        const uint32_t dbase = sb + 1024 + stage * PSTAGE;
        #pragma unroll
        for (int i = 0; i < 6; i++) {
            const int tile = i >> 1;
            const int r = (i & 1) * 64 + cr;
            const uint32_t dst = dbase + tile * PTILE + r * PROWB + cu;
            const __half* src;
            if (tile == 0)      src = Ah + (size_t)(m0 + r) * CC + k0;
            else if (tile == 1) src = Al + (size_t)(m0 + r) * CC + k0;
            else                src = Bh + (size_t)(n0 + r) * CC + k0;
            cp_async16(dst, (const char*)src + cu);
        }
    };

    issue_stage(0, 0); CP_COMMIT();
    issue_stage(1, 1); CP_COMMIT();

    if (tid < 128) {
        bias_s[tid] = bias[n0 + tid];
        if (SCATTER) rowidx[tid] = order[m0 + tid];
    }
    __syncthreads();

    const int wm = (wid & 1) * 64;
    const int wn = (wid >> 1) * 32;

    float acc[4][4][4];
    #pragma unroll
    for (int nt = 0; nt < 4; nt++) {
        float b0 = bias_s[wn + nt * 8 + 2 * (lane & 3)];
        float b1 = bias_s[wn + nt * 8 + 2 * (lane & 3) + 1];
        #pragma unroll
        for (int mt = 0; mt < 4; mt++) {
            acc[mt][nt][0] = b0; acc[mt][nt][1] = b1;
            acc[mt][nt][2] = b0; acc[mt][nt][3] = b1;
        }
    }

    const uint32_t a_lm = sb + 1024 + (wm + (lane & 15)) * PROWB + ((lane >> 4) & 1) * 16;
    const uint32_t b_lm = sb + 1024 + 2 * PTILE + (wn + (lane & 7)) * PROWB
                          + ((lane >> 3) & 1) * 16;

    const int NC = CC / 32;   // 16
    #pragma unroll 1
    for (int c = 0; c < NC; c++) {
        CP_WAIT1();
        __syncthreads();
        if (c + 2 < NC) issue_stage(c + 2, (c + 2) % 3);
        CP_COMMIT();

        const uint32_t abase = a_lm + (c % 3) * PSTAGE;
        const uint32_t bbase = b_lm + (c % 3) * PSTAGE;
        #pragma unroll
        for (int ks = 0; ks < 2; ks++) {
            const int ko = ks * 32;
            uint32_t ah[4][4], al[4][4], bh[4][2];
            #pragma unroll
            for (int mt = 0; mt < 4; mt++) {
                ldsm_x4(ah[mt], abase + mt * 16 * PROWB + ko);
                ldsm_x4(al[mt], abase + PTILE + mt * 16 * PROWB + ko);
            }
            #pragma unroll
            for (int nt = 0; nt < 4; nt++)
                ldsm_x2(bh[nt], bbase + nt * 8 * PROWB + ko);
            #pragma unroll
            for (int mt = 0; mt < 4; mt++)
                #pragma unroll
                for (int nt = 0; nt < 4; nt++) {
                    mma_f16(acc[mt][nt], ah[mt], bh[nt]);
                    mma_f16(acc[mt][nt], al[mt], bh[nt]);
                }
        }
    }

    #pragma unroll
    for (int mt = 0; mt < 4; mt++) {
        int lrow = wm + mt * 16 + (lane >> 2);
        int d0 = SCATTER ? rowidx[lrow]     : (m0 + lrow);
        int d1 = SCATTER ? rowidx[lrow + 8] : (m0 + lrow + 8);
        #pragma unroll
        for (int nt = 0; nt < 4; nt++) {
            int col = n0 + wn + nt * 8 + 2 * (lane & 3);
            *(float2*)(C + (size_t)d0 * Ntot + col) =
                make_float2(acc[mt][nt][0], acc[mt][nt][1]);
            *(float2*)(C + (size_t)d1 * Ntot + col) =
                make_float2(acc[mt][nt][2], acc[mt][nt][3]);
        }
    }
}

// ---------------- cls qkv: parallel k-split, grid 48 ----------------
__global__ __launch_bounds__(256)
void cls_qkv_kernel(const float* __restrict__ cls_tokens,
                    const float* __restrict__ Wqkv,
                    const float* __restrict__ bqkv)
{
    __shared__ float ct[BB * CC];
    __shared__ float red[8][BB][32];
    const int tid = threadIdx.x, lane = tid & 31, seg = tid >> 5;
    for (int i = tid; i < BB * CC; i += 256) ct[i] = cls_tokens[i];
    __syncthreads();
    const int n = blockIdx.x * 32 + lane;
    float acc[BB] = {0.f, 0.f, 0.f, 0.f};
    for (int k = seg * 64; k < seg * 64 + 64; k++) {
        float w = Wqkv[(size_t)k * C3 + n];
        #pragma unroll
        for (int b = 0; b < BB; b++) acc[b] += ct[b * CC + k] * w;
    }
    #pragma unroll
    for (int b = 0; b < BB; b++) red[seg][b][lane] = acc[b];
    __syncthreads();
    if (seg < BB) {
        float s = bqkv[n];
        #pragma unroll
        for (int j = 0; j < 8; j++) s += red[j][seg][lane];
        g_clsqkv[seg * C3 + n] = s;
    }
}

// ---------------- tensor-core attention (token queries), fp16 2-term ----------------
#define NP 272
#define KROWB 144
#define ATT_SMEM (2 * NP * KROWB)   // 78336  (Kh | Vh)

__global__ __launch_bounds__(256)
void attn_mma_kernel(const int* __restrict__ offset)
{
    extern __shared__ char sm[];
    char* KhB = sm;
    char* VhB = sm + NP * KROWB;
    const uint32_t sb = smem_u32(sm);
    const uint32_t KhU = sb;
    const uint32_t VhU = sb + NP * KROWB;

    const int ci = blockIdx.x, h = blockIdx.y, tid = threadIdx.x;
    const int wid = tid >> 5, lane = tid & 31;
    const int cs = ci * KK;
    int b = 0;
    #pragma unroll
    for (int j = 0; j < BB; j++) b += (offset[j] <= cs) ? 1 : 0;
    const float* qkvbase = g_qkv + (size_t)cs * C3;
    const float* clsrow  = g_clsqkv + b * C3;
    const int koff = CC + h * DH, voff = 2 * CC + h * DH;

    // load K,V rows -> smem fp16 (hi only)
    for (int idx = tid; idx < 2 * NP * 16; idx += 256) {
        int kv = idx >= NP * 16;
        int i  = kv ? idx - NP * 16 : idx;
        int t = i >> 4, d4 = (i & 15) << 2;
        int off = kv ? voff : koff;
        float4 v = make_float4(0.f, 0.f, 0.f, 0.f);
        if (t == 0)       v = *(const float4*)(clsrow + off + d4);
        else if (t <= KK) v = *(const float4*)(qkvbase + (size_t)(t - 1) * C3 + off + d4);
        __half2 h01 = __floats2half2_rn(v.x, v.y);
        __half2 h23 = __floats2half2_rn(v.z, v.w);
        char* hB = (kv ? VhB : KhB) + t * KROWB + d4 * 2;
        *(uint2*)hB = make_uint2(*(uint32_t*)&h01, *(uint32_t*)&h23);
    }
    __syncthreads();

    const int r0 = lane >> 2;
    const int qp = (lane & 3) * 2;

    #pragma unroll 1
    for (int mt = wid; mt < 16; mt += 8) {
        const float* p0 = qkvbase + (size_t)(mt * 16 + r0) * C3 + h * DH;
        const float* p1 = p0 + 8 * C3;

        float acc[34][4];
        #pragma unroll
        for (int nt = 0; nt < 34; nt++)
            acc[nt][0] = acc[nt][1] = acc[nt][2] = acc[nt][3] = 0.f;

        // ---- S = Q K^T (Q split hi/lo, K hi) ----
        #pragma unroll
        for (int kt = 0; kt < 4; kt++) {
            float2 q00 = *(const float2*)(p0 + kt * 16 + qp);
            float2 q10 = *(const float2*)(p1 + kt * 16 + qp);
            float2 q01 = *(const float2*)(p0 + kt * 16 + qp + 8);
            float2 q11 = *(const float2*)(p1 + kt * 16 + qp + 8);
            uint32_t qh[4], ql[4];
            qh[0] = split_pack_h(q00.x * 0.125f, q00.y * 0.125f, &ql[0]);
            qh[1] = split_pack_h(q10.x * 0.125f, q10.y * 0.125f, &ql[1]);
            qh[2] = split_pack_h(q01.x * 0.125f, q01.y * 0.125f, &ql[2]);
            qh[3] = split_pack_h(q11.x * 0.125f, q11.y * 0.125f, &ql[3]);
            const uint32_t kaddr = KhU + (lane & 7) * KROWB + ((lane >> 3) & 1) * 16 + kt * 32;
            #pragma unroll
            for (int nt = 0; nt < 34; nt++) {
                uint32_t bh[2];
                ldsm_x2(bh, kaddr + nt * 8 * KROWB);
                mma_f16(acc[nt], qh, bh);
                mma_f16(acc[nt], ql, bh);
            }
        }

        // mask invalid key columns (col > 256)
        if (qp != 0) { acc[32][0] = -1e30f; acc[32][2] = -1e30f; }
        acc[32][1] = -1e30f; acc[32][3] = -1e30f;
        acc[33][0] = acc[33][1] = acc[33][2] = acc[33][3] = -1e30f;

        // softmax
        float m0 = -1e30f, m1 = -1e30f;
        #pragma unroll
        for (int nt = 0; nt < 34; nt++) {
            m0 = fmaxf(m0, fmaxf(acc[nt][0], acc[nt][1]));
            m1 = fmaxf(m1, fmaxf(acc[nt][2], acc[nt][3]));
        }
        m0 = fmaxf(m0, __shfl_xor_sync(0xffffffffu, m0, 1));
        m0 = fmaxf(m0, __shfl_xor_sync(0xffffffffu, m0, 2));
        m1 = fmaxf(m1, __shfl_xor_sync(0xffffffffu, m1, 1));
        m1 = fmaxf(m1, __shfl_xor_sync(0xffffffffu, m1, 2));
        float s0 = 0.f, s1 = 0.f;
        #pragma unroll
        for (int nt = 0; nt < 34; nt++) {
            acc[nt][0] = __expf(acc[nt][0] - m0);
            acc[nt][1] = __expf(acc[nt][1] - m0);
            acc[nt][2] = __expf(acc[nt][2] - m1);
            acc[nt][3] = __expf(acc[nt][3] - m1);
            s0 += acc[nt][0] + acc[nt][1];
            s1 += acc[nt][2] + acc[nt][3];
        }
        s0 += __shfl_xor_sync(0xffffffffu, s0, 1);
        s0 += __shfl_xor_sync(0xffffffffu, s0, 2);
        s1 += __shfl_xor_sync(0xffffffffu, s1, 1);
        s1 += __shfl_xor_sync(0xffffffffu, s1, 2);
        const float inv0 = 1.f / s0, inv1 = 1.f / s1;

        // ---- O = P V (P split hi/lo, V hi) ----
        float o[8][4];
        #pragma unroll
        for (int nt = 0; nt < 8; nt++)
            o[nt][0] = o[nt][1] = o[nt][2] = o[nt][3] = 0.f;

        #pragma unroll
        for (int kt = 0; kt < 17; kt++) {
            uint32_t ah[4], al[4];
            ah[0] = split_pack_h(acc[2*kt][0] * inv0,   acc[2*kt][1] * inv0,   &al[0]);
            ah[1] = split_pack_h(acc[2*kt][2] * inv1,   acc[2*kt][3] * inv1,   &al[1]);
            ah[2] = split_pack_h(acc[2*kt+1][0] * inv0, acc[2*kt+1][1] * inv0, &al[2]);
            ah[3] = split_pack_h(acc[2*kt+1][2] * inv1, acc[2*kt+1][3] * inv1, &al[3]);
            const uint32_t vaddr = VhU + (kt * 16 + (lane & 15)) * KROWB;
            #pragma unroll
            for (int nt = 0; nt < 8; nt++) {
                uint32_t bh[2];
                ldsm_x2_t(bh, vaddr + nt * 16);
                mma_f16(o[nt], ah, bh);
                mma_f16(o[nt], al, bh);
            }
        }

        // store split fp16 hi/lo
        const size_t row0 = (size_t)(cs + mt * 16 + r0) * CC + h * DH;
        const size_t row1 = row0 + 8 * CC;
        #pragma unroll
        for (int nt = 0; nt < 8; nt++) {
            uint32_t lo;
            uint32_t hi = split_pack_h(o[nt][0], o[nt][1], &lo);
            *(uint32_t*)(g_att_h + row0 + nt * 8 + qp) = hi;
            *(uint32_t*)(g_att_l + row0 + nt * 8 + qp) = lo;
            hi = split_pack_h(o[nt][2], o[nt][3], &lo);
            *(uint32_t*)(g_att_h + row1 + nt * 8 + qp) = hi;
            *(uint32_t*)(g_att_l + row1 + nt * 8 + qp) = lo;
        }
    }
}

// ---------------- cls-query attention ----------------
__global__ __launch_bounds__(256)
void cls_attn_kernel(const int* __restrict__ offset)
{
    __shared__ float sS[HH][257];
    const int ci = blockIdx.x, tid = threadIdx.x;
    const int h = tid >> 5, lane = tid & 31;
    const int cs = ci * KK;
    int b = 0;
    #pragma unroll
    for (int j = 0; j < BB; j++) b += (offset[j] <= cs) ? 1 : 0;
    const float* qkvbase = g_qkv + (size_t)cs * C3;
    const float* clsrow  = g_clsqkv + b * C3;
    const int koff = CC + h * DH, voff = 2 * CC + h * DH;

    const float q0 = clsrow[h * DH + lane] * 0.125f;
    const float q1 = clsrow[h * DH + lane + 32] * 0.125f;

    for (int j = 0; j < 257; j++) {
        const float* kr = (j == 0) ? (clsrow + koff)
                                   : (qkvbase + (size_t)(j - 1) * C3 + koff);
        float part = q0 * kr[lane] + q1 * kr[lane + 32];
        #pragma unroll
        for (int o = 16; o; o >>= 1) part += __shfl_xor_sync(0xffffffffu, part, o);
        if (lane == 0) sS[h][j] = part;
    }
    __syncwarp();

    float m = -1e30f;
    for (int j = lane; j < 257; j += 32) m = fmaxf(m, sS[h][j]);
    #pragma unroll
    for (int o = 16; o; o >>= 1) m = fmaxf(m, __shfl_xor_sync(0xffffffffu, m, o));
    float s = 0.f;
    for (int j = lane; j < 257; j += 32) {
        float e = __expf(sS[h][j] - m);
        sS[h][j] = e;
        s += e;
    }
    #pragma unroll
    for (int o = 16; o; o >>= 1) s += __shfl_xor_sync(0xffffffffu, s, o);
    const float inv = 1.f / s;
    __syncwarp();

    float o0 = 0.f, o1 = 0.f;
    for (int j = 0; j < 257; j++) {
        const float* vr = (j == 0) ? (clsrow + voff)
                                   : (qkvbase + (size_t)(j - 1) * C3 + voff);
        float p = sS[h][j] * inv;
        o0 += p * vr[lane];
        o1 += p * vr[lane + 32];
    }
    g_clspart[ci * CC + h * DH + lane]      = o0;
    g_clspart[ci * CC + h * DH + lane + 32] = o1;
}

// ---------------- cls reduce ----------------
__global__ __launch_bounds__(256)
void cls_reduce_kernel(const int* __restrict__ offset, float* __restrict__ out_cls)
{
    int gid = blockIdx.x * 256 + threadIdx.x;
    int b = gid >> 9;
    int c = gid & (CC - 1);
    int start = (b == 0) ? 0 : offset[b - 1];
    int end = offset[b];
    int ch0 = start / KK, ch1 = end / KK;
    float s = 0.f;
    for (int ch = ch0; ch < ch1; ch++) s += g_clspart[ch * CC + c];
    out_cls[gid] = s / (float)(ch1 - ch0);
}

// ---------------- launch ----------------
extern "C" void kernel_launch(void* const* d_in, const int* in_sizes, int n_in,
                              void* d_out, int out_size)
{
    const float* feat       = (const float*)d_in[0];
    const float* cls_tokens = (const float*)d_in[1];
    const float* Wqkv       = (const float*)d_in[2];
    const float* bqkv       = (const float*)d_in[3];
    const float* Wproj      = (const float*)d_in[4];
    const float* bproj      = (const float*)d_in[5];
    const int*   order      = (const int*)d_in[6];
    const int*   offset     = (const int*)d_in[8];

    float* out_feat = (float*)d_out;
    float* out_cls  = out_feat + (size_t)NPTS * CC;

    void *qkvp = nullptr;
    void *ah = nullptr, *al = nullptr, *ath = nullptr, *atl = nullptr;
    void *wq = nullptr, *wp = nullptr;
    cudaGetSymbolAddress(&qkvp, g_qkv);
    cudaGetSymbolAddress(&ah, g_Ah);
    cudaGetSymbolAddress(&al, g_Al);
    cudaGetSymbolAddress(&ath, g_att_h);
    cudaGetSymbolAddress(&atl, g_att_l);
    cudaGetSymbolAddress(&wq, g_WqkvT);
    cudaGetSymbolAddress(&wp, g_WprojT);

    cudaFuncSetAttribute(attn_mma_kernel, cudaFuncAttributeMaxDynamicSharedMemorySize,
                         ATT_SMEM);
    cudaFuncSetAttribute(gemm_async_kernel<false>,
                         cudaFuncAttributeMaxDynamicSharedMemorySize, GSMEM);
    cudaFuncSetAttribute(gemm_async_kernel<true>,
                         cudaFuncAttributeMaxDynamicSharedMemorySize, GSMEM);

    // 0. weight transpose (fp16), feat gather+split (fp16)
    conv_wt_kernel<<<dim3(C3 / 32, CC / 32), 256>>>(Wqkv, (__half*)wq, CC, C3);
    conv_wt_kernel<<<dim3(CC / 32, CC / 32), 256>>>(Wproj, (__half*)wp, CC, CC);
    conv_feat_kernel<<<(NPTS * (CC / 4)) / 256, 256>>>(feat, order);
    // 1. cls token qkv
    cls_qkv_kernel<<<C3 / 32, 256>>>(cls_tokens, Wqkv, bqkv);
    // 2. qkv GEMM
    gemm_async_kernel<false><<<dim3(C3 / 128, NPTS / 128), 256, GSMEM>>>(
        (const __half*)ah, (const __half*)al, (const __half*)wq,
        bqkv, (float*)qkvp, order, C3);
    // 3. attention
    attn_mma_kernel<<<dim3(NCH, HH), 256, ATT_SMEM>>>(offset);
    cls_attn_kernel<<<NCH, 256>>>(offset);
    // 4. proj GEMM with scatter
    gemm_async_kernel<true><<<dim3(CC / 128, NPTS / 128), 256, GSMEM>>>(
        (const __half*)ath, (const __half*)atl, (const __half*)wp,
        bproj, out_feat, order, CC);
    // 5. cls reduction
    cls_reduce_kernel<<<(BB * CC) / 256, 256>>>(offset, out_cls);
}